// round 2
// baseline (speedup 1.0000x reference)
#include <cuda_runtime.h>
#include <cuda_fp16.h>
#include <mma.h>
#include <math.h>

using namespace nvcuda;

// Problem constants
#define NH   16
#define NKV  4
#define HD   128
#define BB   2
#define SEQ  2048
#define HID  2048
#define MROWS (BB*SEQ)          // 4096

// ---------------- device scratch (static, no allocs) ----------------
__device__ __half g_hX [MROWS*HID];          // hidden in fp16
__device__ __half g_Wq [NH*HD*HID];
__device__ __half g_Wk [NKV*HD*HID];
__device__ __half g_Wv [NKV*HD*HID];
__device__ __half g_Wo [HID*NH*HD];
__device__ float  g_qf [MROWS*NH*HD];        // q projection (fp32)
__device__ float  g_kf [MROWS*NKV*HD];
__device__ float  g_vf [MROWS*NKV*HD];
__device__ __half g_Q  [BB*NH*SEQ*HD];       // [b,h,s,d], roped, pre-scaled
__device__ __half g_K  [BB*NKV*SEQ*HD];      // [b,kv,s,d], roped
__device__ __half g_V  [BB*NKV*SEQ*HD];      // [b,kv,s,d]
__device__ __half g_attn[MROWS*NH*HD];       // attention output, [b*s, h*d]
__device__ float  g_cos[SEQ*64];
__device__ float  g_sin[SEQ*64];

// ---------------- elementwise: float -> half ----------------
__global__ void f2h_kernel(const float* __restrict__ src, __half* __restrict__ dst, int n)
{
    int i = blockIdx.x * blockDim.x + threadIdx.x;
    if (i < n) dst[i] = __float2half(src[i]);
}

// ---------------- RoPE cos/sin table (double precision phase) ----------------
__global__ void tab_kernel()
{
    int tid = blockIdx.x * blockDim.x + threadIdx.x;
    if (tid >= SEQ * 64) return;
    int s = tid / 64, i = tid % 64;
    double inv = pow(10000.0, -(double)i / 64.0);
    double ang = (double)s * inv;
    double sn, cs;
    sincos(ang, &sn, &cs);
    g_cos[tid] = (float)cs;
    g_sin[tid] = (float)sn;
}

// ---------------- RoPE + transpose to [b,h,s,d] ----------------
__global__ void rope_kernel(const float* __restrict__ lin, __half* __restrict__ dst,
                            int nheads, float scale)
{
    int tid = blockIdx.x * blockDim.x + threadIdx.x;
    int total = BB * SEQ * nheads * 64;
    if (tid >= total) return;
    int i = tid & 63;
    int h = (tid >> 6) % nheads;
    int s = (tid / (64 * nheads)) % SEQ;
    int b = tid / (64 * nheads * SEQ);
    const float* p = lin + ((size_t)(b * SEQ + s) * nheads + h) * HD;
    float x1 = p[i], x2 = p[i + 64];
    float c = g_cos[s * 64 + i], sn = g_sin[s * 64 + i];
    __half* o = dst + ((size_t)(b * nheads + h) * SEQ + s) * HD;
    o[i]      = __float2half((x1 * c - x2 * sn) * scale);
    o[i + 64] = __float2half((x2 * c + x1 * sn) * scale);
}

// ---------------- V transpose to [b,kv,s,d] ----------------
__global__ void vtrans_kernel(const float* __restrict__ lin, __half* __restrict__ dst)
{
    int tid = blockIdx.x * blockDim.x + threadIdx.x;
    int total = BB * SEQ * NKV * HD;
    if (tid >= total) return;
    int d  = tid % HD;
    int t2 = tid / HD;
    int kv = t2 % NKV;
    int t3 = t2 / NKV;
    int s  = t3 % SEQ;
    int b  = t3 / SEQ;
    dst[((size_t)(b * NKV + kv) * SEQ + s) * HD + d] = __float2half(lin[tid]);
}

// ---------------- Tensor-core TN GEMM: C[M,N] = A[M,K] * B[N,K]^T ----------------
// A,B half row-major (K contiguous), C float row-major. fp32 accumulate.
#define BM 128
#define BN 128
#define BK 32
#define SKA 40   // smem leading dim (half), 80B row stride

__global__ void __launch_bounds__(256) gemm_tn(const __half* __restrict__ A,
                                               const __half* __restrict__ Bm,
                                               float* __restrict__ C,
                                               int M, int N, int K)
{
    __shared__ __half sA[BM * SKA];
    __shared__ __half sB[BN * SKA];
    int m0 = blockIdx.y * BM, n0 = blockIdx.x * BN;
    int tid = threadIdx.x;
    int w = tid >> 5, wm = w >> 2, wn = w & 3;   // 2x4 warp grid, warp tile 64x32

    wmma::fragment<wmma::accumulator, 16, 16, 16, float> acc[4][2];
#pragma unroll
    for (int i = 0; i < 4; i++)
#pragma unroll
        for (int j = 0; j < 2; j++) wmma::fill_fragment(acc[i][j], 0.0f);

    for (int k0 = 0; k0 < K; k0 += BK) {
#pragma unroll
        for (int u = tid; u < BM * BK / 4; u += 256) {
            int r = u >> 3, c = u & 7;
            *(uint2*)(sA + r * SKA + c * 4) =
                *(const uint2*)(A + (size_t)(m0 + r) * K + k0 + c * 4);
        }
#pragma unroll
        for (int u = tid; u < BN * BK / 4; u += 256) {
            int r = u >> 3, c = u & 7;
            *(uint2*)(sB + r * SKA + c * 4) =
                *(const uint2*)(Bm + (size_t)(n0 + r) * K + k0 + c * 4);
        }
        __syncthreads();
#pragma unroll
        for (int kk = 0; kk < BK; kk += 16) {
            wmma::fragment<wmma::matrix_a, 16, 16, 16, __half, wmma::row_major> af[4];
            wmma::fragment<wmma::matrix_b, 16, 16, 16, __half, wmma::col_major> bf[2];
#pragma unroll
            for (int i = 0; i < 4; i++)
                wmma::load_matrix_sync(af[i], sA + (wm * 64 + i * 16) * SKA + kk, SKA);
#pragma unroll
            for (int j = 0; j < 2; j++)
                wmma::load_matrix_sync(bf[j], sB + (wn * 32 + j * 16) * SKA + kk, SKA);
#pragma unroll
            for (int i = 0; i < 4; i++)
#pragma unroll
                for (int j = 0; j < 2; j++)
                    wmma::mma_sync(acc[i][j], af[i], bf[j], acc[i][j]);
        }
        __syncthreads();
    }
#pragma unroll
    for (int i = 0; i < 4; i++)
#pragma unroll
        for (int j = 0; j < 2; j++)
            wmma::store_matrix_sync(C + (size_t)(m0 + wm * 64 + i * 16) * N
                                      + n0 + wn * 32 + j * 16,
                                    acc[i][j], N, wmma::mem_row_major);
}

// ---------------- Flash attention, full (non-causal) softmax ----------------
// grid: (SEQ/64, B*NH), 256 threads. Q pre-scaled by 1/sqrt(HD).
#define TQ  64
#define TK  64
#define SQL 136   // half ldm for Q/K/V tiles (272B rows)
#define SSL 68    // float ldm for scores
#define SPL 72    // half ldm for P
#define SOL 132   // float ldm for O accumulator

#define ATTN_SMEM (3*(TQ*SQL*2) + TQ*SSL*4 + TQ*SPL*2 + TQ*SOL*4 + 3*TQ*4)

__global__ void __launch_bounds__(256) attn_kernel()
{
    extern __shared__ __align__(16) char smem_raw[];
    __half* sQ = (__half*)smem_raw;
    __half* sK = sQ + TQ * SQL;
    __half* sV = sK + TK * SQL;
    float*  sS = (float*)(sV + TK * SQL);
    __half* sP = (__half*)(sS + TQ * SSL);
    float*  sO = (float*)(sP + TQ * SPL);
    float*  m_s   = sO + TQ * SOL;
    float*  l_s   = m_s + TQ;
    float*  fac_s = l_s + TQ;

    int tid = threadIdx.x;
    int q0  = blockIdx.x * TQ;
    int bh  = blockIdx.y;
    int b = bh / NH, h = bh % NH;
    int kvh = h / (NH / NKV);

    const __half* Qg = g_Q + ((size_t)bh * SEQ + q0) * HD;
    const __half* Kg = g_K + ((size_t)(b * NKV + kvh) * SEQ) * HD;
    const __half* Vg = g_V + ((size_t)(b * NKV + kvh) * SEQ) * HD;

    for (int u = tid; u < TQ * HD / 4; u += 256) {
        int r = u >> 5, c = u & 31;
        *(uint2*)(sQ + r * SQL + c * 4) = *(const uint2*)(Qg + r * HD + c * 4);
    }
    for (int r = tid; r < TQ; r += 256) { m_s[r] = -1e30f; l_s[r] = 0.0f; }
    for (int e = tid; e < TQ * HD; e += 256) sO[(e >> 7) * SOL + (e & 127)] = 0.0f;
    __syncthreads();

    int w = tid >> 5;
    int wms = w >> 1, wns = w & 1;   // scores: 4x2 warp grid (16q x 32k per warp)
    int wmp = w >> 2, wnp = w & 3;   // PV:     2x4 warp grid (32q x 32d per warp)

    for (int kt = 0; kt < SEQ / TK; kt++) {
        const __half* Kt = Kg + (size_t)kt * TK * HD;
        const __half* Vt = Vg + (size_t)kt * TK * HD;
        for (int u = tid; u < TK * HD / 4; u += 256) {
            int r = u >> 5, c = u & 31;
            *(uint2*)(sK + r * SQL + c * 4) = *(const uint2*)(Kt + r * HD + c * 4);
            *(uint2*)(sV + r * SQL + c * 4) = *(const uint2*)(Vt + r * HD + c * 4);
        }
        __syncthreads();

        // S = Q @ K^T  (fp32 accum)
        {
            wmma::fragment<wmma::accumulator, 16, 16, 16, float> acc[2];
            wmma::fill_fragment(acc[0], 0.0f);
            wmma::fill_fragment(acc[1], 0.0f);
#pragma unroll
            for (int d = 0; d < HD; d += 16) {
                wmma::fragment<wmma::matrix_a, 16, 16, 16, __half, wmma::row_major> af;
                wmma::load_matrix_sync(af, sQ + (wms * 16) * SQL + d, SQL);
#pragma unroll
                for (int j = 0; j < 2; j++) {
                    wmma::fragment<wmma::matrix_b, 16, 16, 16, __half, wmma::col_major> bf;
                    wmma::load_matrix_sync(bf, sK + (wns * 32 + j * 16) * SQL + d, SQL);
                    wmma::mma_sync(acc[j], af, bf, acc[j]);
                }
            }
#pragma unroll
            for (int j = 0; j < 2; j++)
                wmma::store_matrix_sync(sS + (wms * 16) * SSL + wns * 32 + j * 16,
                                        acc[j], SSL, wmma::mem_row_major);
        }
        __syncthreads();

        // online softmax: 4 threads per query row
        {
            int r = tid >> 2, c4 = tid & 3;
            float mx = -1e30f;
#pragma unroll
            for (int c = 0; c < 16; c++) mx = fmaxf(mx, sS[r * SSL + c4 * 16 + c]);
            mx = fmaxf(mx, __shfl_xor_sync(0xffffffffu, mx, 1));
            mx = fmaxf(mx, __shfl_xor_sync(0xffffffffu, mx, 2));
            float mo = m_s[r];
            float mn = fmaxf(mo, mx);
            float sum = 0.0f;
#pragma unroll
            for (int c = 0; c < 16; c++) {
                float p = __expf(sS[r * SSL + c4 * 16 + c] - mn);
                sP[r * SPL + c4 * 16 + c] = __float2half(p);
                sum += p;
            }
            sum += __shfl_xor_sync(0xffffffffu, sum, 1);
            sum += __shfl_xor_sync(0xffffffffu, sum, 2);
            if (c4 == 0) {
                float fac = __expf(mo - mn);     // mo=-1e30 -> 0
                fac_s[r] = fac;
                l_s[r] = l_s[r] * fac + sum;
                m_s[r] = mn;
            }
        }
        __syncthreads();

        // rescale running O
        for (int e = tid; e < TQ * HD; e += 256) {
            int r = e >> 7, c = e & 127;
            sO[r * SOL + c] *= fac_s[r];
        }
        __syncthreads();

        // O += P @ V
        {
            wmma::fragment<wmma::accumulator, 16, 16, 16, float> acc[2][2];
#pragma unroll
            for (int i = 0; i < 2; i++)
#pragma unroll
                for (int j = 0; j < 2; j++)
                    wmma::load_matrix_sync(acc[i][j],
                        sO + (wmp * 32 + i * 16) * SOL + wnp * 32 + j * 16,
                        SOL, wmma::mem_row_major);
#pragma unroll
            for (int kk = 0; kk < TK; kk += 16) {
                wmma::fragment<wmma::matrix_a, 16, 16, 16, __half, wmma::row_major> af[2];
                wmma::fragment<wmma::matrix_b, 16, 16, 16, __half, wmma::row_major> bf[2];
#pragma unroll
                for (int i = 0; i < 2; i++)
                    wmma::load_matrix_sync(af[i], sP + (wmp * 32 + i * 16) * SPL + kk, SPL);
#pragma unroll
                for (int j = 0; j < 2; j++)
                    wmma::load_matrix_sync(bf[j], sV + kk * SQL + wnp * 32 + j * 16, SQL);
#pragma unroll
                for (int i = 0; i < 2; i++)
#pragma unroll
                    for (int j = 0; j < 2; j++)
                        wmma::mma_sync(acc[i][j], af[i], bf[j], acc[i][j]);
            }
#pragma unroll
            for (int i = 0; i < 2; i++)
#pragma unroll
                for (int j = 0; j < 2; j++)
                    wmma::store_matrix_sync(
                        sO + (wmp * 32 + i * 16) * SOL + wnp * 32 + j * 16,
                        acc[i][j], SOL, wmma::mem_row_major);
        }
        __syncthreads();
    }

    // normalize and write back in [b*s, h*d] layout (half) for the final GEMM
    __half* Og = g_attn + ((size_t)(b * SEQ + q0)) * (NH * HD) + h * HD;
    for (int e = tid; e < TQ * HD; e += 256) {
        int r = e >> 7, c = e & 127;
        Og[(size_t)r * (NH * HD) + c] = __float2half(sO[r * SOL + c] / l_s[r]);
    }
}

// ---------------- launch ----------------
extern "C" void kernel_launch(void* const* d_in, const int* in_sizes, int n_in,
                              void* d_out, int out_size)
{
    const float* hidden = (const float*)d_in[0];
    const float* Wq = (const float*)d_in[1];
    const float* Wk = (const float*)d_in[2];
    const float* Wv = (const float*)d_in[3];
    const float* Wo = (const float*)d_in[4];
    float* out = (float*)d_out;

    cudaFuncSetAttribute(attn_kernel, cudaFuncAttributeMaxDynamicSharedMemorySize, ATTN_SMEM);

    __half *p_hX, *p_Wq, *p_Wk, *p_Wv, *p_Wo, *p_attn;
    float *p_qf, *p_kf, *p_vf;
    cudaGetSymbolAddress((void**)&p_hX,  g_hX);
    cudaGetSymbolAddress((void**)&p_Wq,  g_Wq);
    cudaGetSymbolAddress((void**)&p_Wk,  g_Wk);
    cudaGetSymbolAddress((void**)&p_Wv,  g_Wv);
    cudaGetSymbolAddress((void**)&p_Wo,  g_Wo);
    cudaGetSymbolAddress((void**)&p_attn, g_attn);
    cudaGetSymbolAddress((void**)&p_qf,  g_qf);
    cudaGetSymbolAddress((void**)&p_kf,  g_kf);
    cudaGetSymbolAddress((void**)&p_vf,  g_vf);

    const int T = 256;
    // fp32 -> fp16 conversions
    f2h_kernel<<<(MROWS*HID + T-1)/T, T>>>(hidden, p_hX, MROWS*HID);
    f2h_kernel<<<(NH*HD*HID + T-1)/T, T>>>(Wq, p_Wq, NH*HD*HID);
    f2h_kernel<<<(NKV*HD*HID + T-1)/T, T>>>(Wk, p_Wk, NKV*HD*HID);
    f2h_kernel<<<(NKV*HD*HID + T-1)/T, T>>>(Wv, p_Wv, NKV*HD*HID);
    f2h_kernel<<<(HID*NH*HD + T-1)/T, T>>>(Wo, p_Wo, HID*NH*HD);

    tab_kernel<<<(SEQ*64 + T-1)/T, T>>>();

    // projections
    gemm_tn<<<dim3((NH*HD)/BN,  MROWS/BM), T>>>(p_hX, p_Wq, p_qf, MROWS, NH*HD,  HID);
    gemm_tn<<<dim3((NKV*HD)/BN, MROWS/BM), T>>>(p_hX, p_Wk, p_kf, MROWS, NKV*HD, HID);
    gemm_tn<<<dim3((NKV*HD)/BN, MROWS/BM), T>>>(p_hX, p_Wv, p_vf, MROWS, NKV*HD, HID);

    // RoPE + layout transforms
    __half *p_Q, *p_K, *p_V;
    cudaGetSymbolAddress((void**)&p_Q, g_Q);
    cudaGetSymbolAddress((void**)&p_K, g_K);
    cudaGetSymbolAddress((void**)&p_V, g_V);
    const float qscale = 0.08838834764831845f;   // 1/sqrt(128)
    rope_kernel<<<(BB*SEQ*NH*64 + T-1)/T, T>>>(p_qf, p_Q, NH, qscale);
    rope_kernel<<<(BB*SEQ*NKV*64 + T-1)/T, T>>>(p_kf, p_K, NKV, 1.0f);
    vtrans_kernel<<<(BB*SEQ*NKV*HD + T-1)/T, T>>>(p_vf, p_V);

    // attention
    attn_kernel<<<dim3(SEQ/TQ, BB*NH), T, ATTN_SMEM>>>();

    // output projection -> fp32 d_out
    gemm_tn<<<dim3(HID/BN, MROWS/BM), T>>>(p_attn, p_Wo, out, MROWS, HID, NH*HD);
}

// round 3
// speedup vs baseline: 1.0671x; 1.0671x over previous
#include <cuda_runtime.h>
#include <cuda_fp16.h>
#include <mma.h>
#include <math.h>

using namespace nvcuda;

// Problem constants
#define NH   16
#define NKV  4
#define HD   128
#define BB   2
#define SEQ  2048
#define HID  2048
#define MROWS (BB*SEQ)          // 4096

// ---------------- device scratch (static, no allocs) ----------------
__device__ __half g_hX [MROWS*HID];          // hidden in fp16
__device__ __half g_Wq [NH*HD*HID];
__device__ __half g_Wkv[(2*NKV*HD)*HID];     // Wk rows then Wv rows (1024 x 2048)
__device__ __half g_Wo [HID*NH*HD];
__device__ float  g_qf [MROWS*NH*HD];        // q projection (fp32)
__device__ float  g_kvf[MROWS*2*NKV*HD];     // k|v projection fused (fp32), row stride 1024
__device__ __half g_Q  [BB*NH*SEQ*HD];       // [b,h,s,d], roped, pre-scaled
__device__ __half g_K  [BB*NKV*SEQ*HD];      // [b,kv,s,d], roped
__device__ __half g_V  [BB*NKV*SEQ*HD];      // [b,kv,s,d]
__device__ __half g_attn[MROWS*NH*HD];       // attention output, [b*s, h*d]
__device__ float  g_cos[SEQ*64];
__device__ float  g_sin[SEQ*64];

// ---------------- cp.async helpers ----------------
__device__ __forceinline__ void cp_async16(void* smem, const void* gmem)
{
    unsigned s = (unsigned)__cvta_generic_to_shared(smem);
    asm volatile("cp.async.cg.shared.global [%0], [%1], 16;\n" :: "r"(s), "l"(gmem));
}
__device__ __forceinline__ void cp_commit() { asm volatile("cp.async.commit_group;\n"); }
template<int N> __device__ __forceinline__ void cp_wait()
{
    asm volatile("cp.async.wait_group %0;\n" :: "n"(N));
}

// ---------------- elementwise: float4 -> half4 ----------------
__global__ void f2h4_kernel(const float4* __restrict__ src, __half* __restrict__ dst, int n4)
{
    int i = blockIdx.x * blockDim.x + threadIdx.x;
    if (i < n4) {
        float4 v = src[i];
        __half2* d = (__half2*)(dst + (size_t)i * 4);
        d[0] = __floats2half2_rn(v.x, v.y);
        d[1] = __floats2half2_rn(v.z, v.w);
    }
}

// ---------------- RoPE cos/sin table (double precision phase) ----------------
__global__ void tab_kernel()
{
    int tid = blockIdx.x * blockDim.x + threadIdx.x;
    if (tid >= SEQ * 64) return;
    int s = tid / 64, i = tid % 64;
    double inv = pow(10000.0, -(double)i / 64.0);
    double ang = (double)s * inv;
    double sn, cs;
    sincos(ang, &sn, &cs);
    g_cos[tid] = (float)cs;
    g_sin[tid] = (float)sn;
}

// ---------------- RoPE + transpose to [b,h,s,d] ----------------
__global__ void rope_kernel(const float* __restrict__ lin, __half* __restrict__ dst,
                            int nheads, int rowstride, float scale)
{
    int tid = blockIdx.x * blockDim.x + threadIdx.x;
    int total = BB * SEQ * nheads * 64;
    if (tid >= total) return;
    int i = tid & 63;
    int h = (tid >> 6) % nheads;
    int s = (tid / (64 * nheads)) % SEQ;
    int b = tid / (64 * nheads * SEQ);
    const float* p = lin + (size_t)(b * SEQ + s) * rowstride + h * HD;
    float x1 = p[i], x2 = p[i + 64];
    float c = g_cos[s * 64 + i], sn = g_sin[s * 64 + i];
    __half* o = dst + ((size_t)(b * nheads + h) * SEQ + s) * HD;
    o[i]      = __float2half((x1 * c - x2 * sn) * scale);
    o[i + 64] = __float2half((x2 * c + x1 * sn) * scale);
}

// ---------------- V transpose to [b,kv,s,d] (reads cols 512.. of fused kv) ----------------
__global__ void vtrans_kernel(const float* __restrict__ lin, __half* __restrict__ dst)
{
    int tid = blockIdx.x * blockDim.x + threadIdx.x;
    int total = BB * SEQ * NKV * HD;
    if (tid >= total) return;
    int d  = tid % HD;
    int t2 = tid / HD;
    int kv = t2 % NKV;
    int t3 = t2 / NKV;
    int s  = t3 % SEQ;
    int b  = t3 / SEQ;
    dst[((size_t)(b * NKV + kv) * SEQ + s) * HD + d] =
        __float2half(lin[(size_t)(b * SEQ + s) * (2 * NKV * HD) + NKV * HD + kv * HD + d]);
}

// ---------------- Pipelined tensor-core TN GEMM: C[M,N] = A[M,K] * B[N,K]^T ----------------
// A,B half row-major (K contiguous), C float row-major. fp32 accumulate.
// cp.async double buffered, BK=64, dynamic smem.
#define BM 128
#define BN 128
#define BK 64
#define SKA 72                      // smem leading dim (half): 144B rows
#define GEMM_SMEM (2*(BM+BN)*SKA*2) // 73728 B

__global__ void __launch_bounds__(256) gemm_tn(const __half* __restrict__ A,
                                               const __half* __restrict__ Bm,
                                               float* __restrict__ C,
                                               int M, int N, int K)
{
    extern __shared__ __align__(16) __half sm[];
    int m0 = blockIdx.y * BM, n0 = blockIdx.x * BN;
    int tid = threadIdx.x;
    int w = tid >> 5, wm = w >> 2, wn = w & 3;   // 2x4 warp grid, warp tile 64x32

    wmma::fragment<wmma::accumulator, 16, 16, 16, float> acc[4][2];
#pragma unroll
    for (int i = 0; i < 4; i++)
#pragma unroll
        for (int j = 0; j < 2; j++) wmma::fill_fragment(acc[i][j], 0.0f);

    const int NKt = K / BK;

    // stage loader: A tile 128x64 + B tile 128x64, 8 halfs per cp.async
    auto load_stage = [&](int s, int k0) {
        __half* sA = sm + (size_t)s * (BM + BN) * SKA;
        __half* sB = sA + BM * SKA;
#pragma unroll
        for (int i = 0; i < 4; i++) {
            int u = tid + i * 256;
            int r = u >> 3, c = (u & 7) * 8;
            cp_async16(sA + r * SKA + c, A + (size_t)(m0 + r) * K + k0 + c);
        }
#pragma unroll
        for (int i = 0; i < 4; i++) {
            int u = tid + i * 256;
            int r = u >> 3, c = (u & 7) * 8;
            cp_async16(sB + r * SKA + c, Bm + (size_t)(n0 + r) * K + k0 + c);
        }
        cp_commit();
    };

    load_stage(0, 0);
    load_stage(1, BK);

    for (int kt = 0; kt < NKt; kt++) {
        if (kt + 1 < NKt) cp_wait<1>(); else cp_wait<0>();
        __syncthreads();

        __half* sA = sm + (size_t)(kt & 1) * (BM + BN) * SKA;
        __half* sB = sA + BM * SKA;
#pragma unroll
        for (int kk = 0; kk < BK; kk += 16) {
            wmma::fragment<wmma::matrix_a, 16, 16, 16, __half, wmma::row_major> af[4];
            wmma::fragment<wmma::matrix_b, 16, 16, 16, __half, wmma::col_major> bf[2];
#pragma unroll
            for (int i = 0; i < 4; i++)
                wmma::load_matrix_sync(af[i], sA + (wm * 64 + i * 16) * SKA + kk, SKA);
#pragma unroll
            for (int j = 0; j < 2; j++)
                wmma::load_matrix_sync(bf[j], sB + (wn * 32 + j * 16) * SKA + kk, SKA);
#pragma unroll
            for (int i = 0; i < 4; i++)
#pragma unroll
                for (int j = 0; j < 2; j++)
                    wmma::mma_sync(acc[i][j], af[i], bf[j], acc[i][j]);
        }
        __syncthreads();
        if (kt + 2 < NKt) load_stage(kt & 1, (kt + 2) * BK);
    }

#pragma unroll
    for (int i = 0; i < 4; i++)
#pragma unroll
        for (int j = 0; j < 2; j++)
            wmma::store_matrix_sync(C + (size_t)(m0 + wm * 64 + i * 16) * N
                                      + n0 + wn * 32 + j * 16,
                                    acc[i][j], N, wmma::mem_row_major);
}

// ---------------- Flash attention, full (non-causal) softmax ----------------
// grid: (SEQ/64, B*NH), 256 threads. Q pre-scaled by 1/sqrt(HD).
// K/V tiles double-buffered via cp.async (2 groups lookahead).
#define TQ  64
#define TK  64
#define SQL 136   // half ldm for Q/K/V tiles (272B rows)
#define SSL 68    // float ldm for scores
#define SPL 72    // half ldm for P
#define SOL 132   // float ldm for O accumulator

// sQ + 2*sK + 2*sV + sS + sP + sO + stats
#define ATTN_SMEM (TQ*SQL*2 + 2*TK*SQL*2 + 2*TK*SQL*2 + TQ*SSL*4 + TQ*SPL*2 + TQ*SOL*4 + 3*TQ*4)

__global__ void __launch_bounds__(256) attn_kernel()
{
    extern __shared__ __align__(16) char smem_raw[];
    __half* sQ  = (__half*)smem_raw;
    __half* sKb = sQ + TQ * SQL;             // 2 stages
    __half* sVb = sKb + 2 * TK * SQL;        // 2 stages
    float*  sS  = (float*)(sVb + 2 * TK * SQL);
    __half* sP  = (__half*)(sS + TQ * SSL);
    float*  sO  = (float*)(sP + TQ * SPL);
    float*  m_s   = sO + TQ * SOL;
    float*  l_s   = m_s + TQ;
    float*  fac_s = l_s + TQ;

    int tid = threadIdx.x;
    int q0  = blockIdx.x * TQ;
    int bh  = blockIdx.y;
    int b = bh / NH, h = bh % NH;
    int kvh = h / (NH / NKV);

    const __half* Qg = g_Q + ((size_t)bh * SEQ + q0) * HD;
    const __half* Kg = g_K + ((size_t)(b * NKV + kvh) * SEQ) * HD;
    const __half* Vg = g_V + ((size_t)(b * NKV + kvh) * SEQ) * HD;

    const int NT = SEQ / TK;

    auto loadK = [&](int t) {
        const __half* src = Kg + (size_t)t * TK * HD;
        __half* dst = sKb + (size_t)(t & 1) * TK * SQL;
#pragma unroll
        for (int i = 0; i < 4; i++) {
            int u = tid + i * 256;
            int r = u >> 4, c = (u & 15) * 8;
            cp_async16(dst + r * SQL + c, src + r * HD + c);
        }
        cp_commit();
    };
    auto loadV = [&](int t) {
        const __half* src = Vg + (size_t)t * TK * HD;
        __half* dst = sVb + (size_t)(t & 1) * TK * SQL;
#pragma unroll
        for (int i = 0; i < 4; i++) {
            int u = tid + i * 256;
            int r = u >> 4, c = (u & 15) * 8;
            cp_async16(dst + r * SQL + c, src + r * HD + c);
        }
        cp_commit();
    };

    // prologue: Q rides in K0's group; then V0, K1, V1
    {
#pragma unroll
        for (int i = 0; i < 4; i++) {
            int u = tid + i * 256;
            int r = u >> 4, c = (u & 15) * 8;
            cp_async16(sQ + r * SQL + c, Qg + r * HD + c);
        }
        loadK(0);   // group0 = {Q, K0}
        loadV(0);   // group1
        loadK(1);   // group2
        loadV(1);   // group3
    }
    for (int r = tid; r < TQ; r += 256) { m_s[r] = -1e30f; l_s[r] = 0.0f; }
    for (int e = tid; e < TQ * HD; e += 256) sO[(e >> 7) * SOL + (e & 127)] = 0.0f;

    int w = tid >> 5;
    int wms = w >> 1, wns = w & 1;   // scores: 4x2 warp grid (16q x 32k per warp)
    int wmp = w >> 2, wnp = w & 3;   // PV:     2x4 warp grid (32q x 32d per warp)

    for (int kt = 0; kt < NT; kt++) {
        if (kt + 1 < NT) cp_wait<2>(); else cp_wait<0>();
        __syncthreads();

        const __half* sK = sKb + (size_t)(kt & 1) * TK * SQL;
        const __half* sV = sVb + (size_t)(kt & 1) * TK * SQL;

        // S = Q @ K^T  (fp32 accum)
        {
            wmma::fragment<wmma::accumulator, 16, 16, 16, float> acc[2];
            wmma::fill_fragment(acc[0], 0.0f);
            wmma::fill_fragment(acc[1], 0.0f);
#pragma unroll
            for (int d = 0; d < HD; d += 16) {
                wmma::fragment<wmma::matrix_a, 16, 16, 16, __half, wmma::row_major> af;
                wmma::load_matrix_sync(af, sQ + (wms * 16) * SQL + d, SQL);
#pragma unroll
                for (int j = 0; j < 2; j++) {
                    wmma::fragment<wmma::matrix_b, 16, 16, 16, __half, wmma::col_major> bf;
                    wmma::load_matrix_sync(bf, sK + (wns * 32 + j * 16) * SQL + d, SQL);
                    wmma::mma_sync(acc[j], af, bf, acc[j]);
                }
            }
#pragma unroll
            for (int j = 0; j < 2; j++)
                wmma::store_matrix_sync(sS + (wms * 16) * SSL + wns * 32 + j * 16,
                                        acc[j], SSL, wmma::mem_row_major);
        }
        __syncthreads();

        // online softmax: 4 threads per query row
        {
            int r = tid >> 2, c4 = tid & 3;
            float mx = -1e30f;
#pragma unroll
            for (int c = 0; c < 16; c++) mx = fmaxf(mx, sS[r * SSL + c4 * 16 + c]);
            mx = fmaxf(mx, __shfl_xor_sync(0xffffffffu, mx, 1));
            mx = fmaxf(mx, __shfl_xor_sync(0xffffffffu, mx, 2));
            float mo = m_s[r];
            float mn = fmaxf(mo, mx);
            float sum = 0.0f;
#pragma unroll
            for (int c = 0; c < 16; c++) {
                float p = __expf(sS[r * SSL + c4 * 16 + c] - mn);
                sP[r * SPL + c4 * 16 + c] = __float2half(p);
                sum += p;
            }
            sum += __shfl_xor_sync(0xffffffffu, sum, 1);
            sum += __shfl_xor_sync(0xffffffffu, sum, 2);
            if (c4 == 0) {
                float fac = __expf(mo - mn);     // mo=-1e30 -> 0
                fac_s[r] = fac;
                l_s[r] = l_s[r] * fac + sum;
                m_s[r] = mn;
            }
        }
        __syncthreads();

        // rescale running O
        for (int e = tid; e < TQ * HD; e += 256) {
            int r = e >> 7, c = e & 127;
            sO[r * SOL + c] *= fac_s[r];
        }
        __syncthreads();

        // O += P @ V
        {
            wmma::fragment<wmma::accumulator, 16, 16, 16, float> acc[2][2];
#pragma unroll
            for (int i = 0; i < 2; i++)
#pragma unroll
                for (int j = 0; j < 2; j++)
                    wmma::load_matrix_sync(acc[i][j],
                        sO + (wmp * 32 + i * 16) * SOL + wnp * 32 + j * 16,
                        SOL, wmma::mem_row_major);
#pragma unroll
            for (int kk = 0; kk < TK; kk += 16) {
                wmma::fragment<wmma::matrix_a, 16, 16, 16, __half, wmma::row_major> af[2];
                wmma::fragment<wmma::matrix_b, 16, 16, 16, __half, wmma::row_major> bf[2];
#pragma unroll
                for (int i = 0; i < 2; i++)
                    wmma::load_matrix_sync(af[i], sP + (wmp * 32 + i * 16) * SPL + kk, SPL);
#pragma unroll
                for (int j = 0; j < 2; j++)
                    wmma::load_matrix_sync(bf[j], sV + kk * SQL + wnp * 32 + j * 16, SQL);
#pragma unroll
                for (int i = 0; i < 2; i++)
#pragma unroll
                    for (int j = 0; j < 2; j++)
                        wmma::mma_sync(acc[i][j], af[i], bf[j], acc[i][j]);
            }
#pragma unroll
            for (int i = 0; i < 2; i++)
#pragma unroll
                for (int j = 0; j < 2; j++)
                    wmma::store_matrix_sync(
                        sO + (wmp * 32 + i * 16) * SOL + wnp * 32 + j * 16,
                        acc[i][j], SOL, wmma::mem_row_major);
        }
        __syncthreads();

        // prefetch tile kt+2 into the buffers we just finished reading
        if (kt + 2 < NT) { loadK(kt + 2); loadV(kt + 2); }
    }

    // normalize and write back in [b*s, h*d] layout (half) for the final GEMM
    __half* Og = g_attn + ((size_t)(b * SEQ + q0)) * (NH * HD) + h * HD;
    for (int e = tid; e < TQ * HD; e += 256) {
        int r = e >> 7, c = e & 127;
        Og[(size_t)r * (NH * HD) + c] = __float2half(sO[r * SOL + c] / l_s[r]);
    }
}

// ---------------- launch ----------------
extern "C" void kernel_launch(void* const* d_in, const int* in_sizes, int n_in,
                              void* d_out, int out_size)
{
    const float* hidden = (const float*)d_in[0];
    const float* Wq = (const float*)d_in[1];
    const float* Wk = (const float*)d_in[2];
    const float* Wv = (const float*)d_in[3];
    const float* Wo = (const float*)d_in[4];
    float* out = (float*)d_out;

    cudaFuncSetAttribute(attn_kernel, cudaFuncAttributeMaxDynamicSharedMemorySize, ATTN_SMEM);
    cudaFuncSetAttribute(gemm_tn, cudaFuncAttributeMaxDynamicSharedMemorySize, GEMM_SMEM);

    __half *p_hX, *p_Wq, *p_Wkv, *p_Wo, *p_attn, *p_Q, *p_K, *p_V;
    float *p_qf, *p_kvf;
    cudaGetSymbolAddress((void**)&p_hX,  g_hX);
    cudaGetSymbolAddress((void**)&p_Wq,  g_Wq);
    cudaGetSymbolAddress((void**)&p_Wkv, g_Wkv);
    cudaGetSymbolAddress((void**)&p_Wo,  g_Wo);
    cudaGetSymbolAddress((void**)&p_attn, g_attn);
    cudaGetSymbolAddress((void**)&p_qf,  g_qf);
    cudaGetSymbolAddress((void**)&p_kvf, g_kvf);
    cudaGetSymbolAddress((void**)&p_Q, g_Q);
    cudaGetSymbolAddress((void**)&p_K, g_K);
    cudaGetSymbolAddress((void**)&p_V, g_V);

    const int T = 256;
    // fp32 -> fp16 conversions (vectorized)
    f2h4_kernel<<<(MROWS*HID/4 + T-1)/T, T>>>((const float4*)hidden, p_hX, MROWS*HID/4);
    f2h4_kernel<<<(NH*HD*HID/4 + T-1)/T, T>>>((const float4*)Wq, p_Wq, NH*HD*HID/4);
    f2h4_kernel<<<(NKV*HD*HID/4 + T-1)/T, T>>>((const float4*)Wk, p_Wkv, NKV*HD*HID/4);
    f2h4_kernel<<<(NKV*HD*HID/4 + T-1)/T, T>>>((const float4*)Wv, p_Wkv + (size_t)NKV*HD*HID, NKV*HD*HID/4);
    f2h4_kernel<<<(HID*NH*HD/4 + T-1)/T, T>>>((const float4*)Wo, p_Wo, HID*NH*HD/4);

    tab_kernel<<<(SEQ*64 + T-1)/T, T>>>();

    // projections: Q (N=2048) and fused KV (N=1024)
    gemm_tn<<<dim3((NH*HD)/BN,  MROWS/BM), T, GEMM_SMEM>>>(p_hX, p_Wq,  p_qf,  MROWS, NH*HD,    HID);
    gemm_tn<<<dim3((2*NKV*HD)/BN, MROWS/BM), T, GEMM_SMEM>>>(p_hX, p_Wkv, p_kvf, MROWS, 2*NKV*HD, HID);

    // RoPE + layout transforms
    const float qscale = 0.08838834764831845f;   // 1/sqrt(128)
    rope_kernel<<<(BB*SEQ*NH*64 + T-1)/T, T>>>(p_qf, p_Q, NH, NH*HD, qscale);
    rope_kernel<<<(BB*SEQ*NKV*64 + T-1)/T, T>>>(p_kvf, p_K, NKV, 2*NKV*HD, 1.0f);
    vtrans_kernel<<<(BB*SEQ*NKV*HD + T-1)/T, T>>>(p_kvf, p_V);

    // attention
    attn_kernel<<<dim3(SEQ/TQ, BB*NH), T, ATTN_SMEM>>>();

    // output projection -> fp32 d_out
    gemm_tn<<<dim3(HID/BN, MROWS/BM), T, GEMM_SMEM>>>(p_attn, p_Wo, out, MROWS, HID, NH*HD);
}

// round 5
// speedup vs baseline: 1.9266x; 1.8055x over previous
#include <cuda_runtime.h>
#include <cuda_fp16.h>
#include <mma.h>
#include <math.h>
#include <stdint.h>
#include <cstdint>

using namespace nvcuda;

#define NH   16
#define NKV  4
#define HD   128
#define BB   2
#define SEQ  2048
#define HID  2048
#define MROWS (BB*SEQ)

// ---------------- device scratch ----------------
__device__ __half g_hX [MROWS*HID];
__device__ __half g_Wq [NH*HD*HID];
__device__ __half g_Wkv[(2*NKV*HD)*HID];
__device__ __half g_Wo [HID*NH*HD];
__device__ float  g_qf [MROWS*NH*HD];
__device__ float  g_kvf[MROWS*2*NKV*HD];
__device__ __half g_Q  [BB*NH*SEQ*HD];
__device__ __half g_K  [BB*NKV*SEQ*HD];
__device__ __half g_V  [BB*NKV*SEQ*HD];
__device__ __half g_attn[MROWS*NH*HD];
__device__ float  g_cos[SEQ*64];
__device__ float  g_sin[SEQ*64];

// ---------------- cp.async helpers ----------------
__device__ __forceinline__ void cp_async16(void* smem, const void* gmem)
{
    unsigned s = (unsigned)__cvta_generic_to_shared(smem);
    asm volatile("cp.async.cg.shared.global [%0], [%1], 16;\n" :: "r"(s), "l"(gmem));
}
__device__ __forceinline__ void cp_commit() { asm volatile("cp.async.commit_group;\n"); }
template<int N> __device__ __forceinline__ void cp_wait()
{
    asm volatile("cp.async.wait_group %0;\n" :: "n"(N));
}

// ---------------- mma / ldmatrix primitives ----------------
__device__ __forceinline__ uint32_t smaddr(const void* p)
{
    return (uint32_t)__cvta_generic_to_shared(p);
}
__device__ __forceinline__ void ldsm_x4(uint32_t a, uint32_t& r0, uint32_t& r1,
                                        uint32_t& r2, uint32_t& r3)
{
    asm volatile("ldmatrix.sync.aligned.m8n8.x4.shared.b16 {%0,%1,%2,%3}, [%4];"
                 : "=r"(r0), "=r"(r1), "=r"(r2), "=r"(r3) : "r"(a));
}
__device__ __forceinline__ void ldsm_x4_t(uint32_t a, uint32_t& r0, uint32_t& r1,
                                          uint32_t& r2, uint32_t& r3)
{
    asm volatile("ldmatrix.sync.aligned.m8n8.x4.trans.shared.b16 {%0,%1,%2,%3}, [%4];"
                 : "=r"(r0), "=r"(r1), "=r"(r2), "=r"(r3) : "r"(a));
}
__device__ __forceinline__ void mma16816(float* c, const uint32_t* a, uint32_t b0, uint32_t b1)
{
    asm volatile("mma.sync.aligned.m16n8k16.row.col.f32.f16.f16.f32 "
                 "{%0,%1,%2,%3}, {%4,%5,%6,%7}, {%8,%9}, {%0,%1,%2,%3};"
                 : "+f"(c[0]), "+f"(c[1]), "+f"(c[2]), "+f"(c[3])
                 : "r"(a[0]), "r"(a[1]), "r"(a[2]), "r"(a[3]), "r"(b0), "r"(b1));
}
__device__ __forceinline__ uint32_t h2pack(float x, float y)
{
    __half2 h = __floats2half2_rn(x, y);
    return *(uint32_t*)&h;
}

// ---------------- elementwise: float4 -> half4 ----------------
__global__ void f2h4_kernel(const float4* __restrict__ src, __half* __restrict__ dst, int n4)
{
    int i = blockIdx.x * blockDim.x + threadIdx.x;
    if (i < n4) {
        float4 v = src[i];
        __half2* d = (__half2*)(dst + (size_t)i * 4);
        d[0] = __floats2half2_rn(v.x, v.y);
        d[1] = __floats2half2_rn(v.z, v.w);
    }
}

// ---------------- RoPE table ----------------
__global__ void tab_kernel()
{
    int tid = blockIdx.x * blockDim.x + threadIdx.x;
    if (tid >= SEQ * 64) return;
    int s = tid / 64, i = tid % 64;
    double inv = pow(10000.0, -(double)i / 64.0);
    double ang = (double)s * inv;
    double sn, cs;
    sincos(ang, &sn, &cs);
    g_cos[tid] = (float)cs;
    g_sin[tid] = (float)sn;
}

// ---------------- RoPE + transpose ----------------
__global__ void rope_kernel(const float* __restrict__ lin, __half* __restrict__ dst,
                            int nheads, int rowstride, float scale)
{
    int tid = blockIdx.x * blockDim.x + threadIdx.x;
    int total = BB * SEQ * nheads * 64;
    if (tid >= total) return;
    int i = tid & 63;
    int h = (tid >> 6) % nheads;
    int s = (tid / (64 * nheads)) % SEQ;
    int b = tid / (64 * nheads * SEQ);
    const float* p = lin + (size_t)(b * SEQ + s) * rowstride + h * HD;
    float x1 = p[i], x2 = p[i + 64];
    float c = g_cos[s * 64 + i], sn = g_sin[s * 64 + i];
    __half* o = dst + ((size_t)(b * nheads + h) * SEQ + s) * HD;
    o[i]      = __float2half((x1 * c - x2 * sn) * scale);
    o[i + 64] = __float2half((x2 * c + x1 * sn) * scale);
}

__global__ void vtrans_kernel(const float* __restrict__ lin, __half* __restrict__ dst)
{
    int tid = blockIdx.x * blockDim.x + threadIdx.x;
    int total = BB * SEQ * NKV * HD;
    if (tid >= total) return;
    int d  = tid % HD;
    int t2 = tid / HD;
    int kv = t2 % NKV;
    int t3 = t2 / NKV;
    int s  = t3 % SEQ;
    int b  = t3 / SEQ;
    dst[((size_t)(b * NKV + kv) * SEQ + s) * HD + d] =
        __float2half(lin[(size_t)(b * SEQ + s) * (2 * NKV * HD) + NKV * HD + kv * HD + d]);
}

// ---------------- Pipelined wmma TN GEMM ----------------
#define BM 128
#define BN 128
#define BK 64
#define SKA 72
#define GEMM_SMEM (2*(BM+BN)*SKA*2)

__global__ void __launch_bounds__(256) gemm_tn(const __half* __restrict__ A,
                                               const __half* __restrict__ Bm,
                                               float* __restrict__ C,
                                               int M, int N, int K)
{
    extern __shared__ __align__(16) __half sm[];
    int m0 = blockIdx.y * BM, n0 = blockIdx.x * BN;
    int tid = threadIdx.x;
    int w = tid >> 5, wm = w >> 2, wn = w & 3;

    wmma::fragment<wmma::accumulator, 16, 16, 16, float> acc[4][2];
#pragma unroll
    for (int i = 0; i < 4; i++)
#pragma unroll
        for (int j = 0; j < 2; j++) wmma::fill_fragment(acc[i][j], 0.0f);

    const int NKt = K / BK;

    auto load_stage = [&](int s, int k0) {
        __half* sA = sm + (size_t)s * (BM + BN) * SKA;
        __half* sB = sA + BM * SKA;
#pragma unroll
        for (int i = 0; i < 4; i++) {
            int u = tid + i * 256;
            int r = u >> 3, c = (u & 7) * 8;
            cp_async16(sA + r * SKA + c, A + (size_t)(m0 + r) * K + k0 + c);
        }
#pragma unroll
        for (int i = 0; i < 4; i++) {
            int u = tid + i * 256;
            int r = u >> 3, c = (u & 7) * 8;
            cp_async16(sB + r * SKA + c, Bm + (size_t)(n0 + r) * K + k0 + c);
        }
        cp_commit();
    };

    load_stage(0, 0);
    load_stage(1, BK);

    for (int kt = 0; kt < NKt; kt++) {
        if (kt + 1 < NKt) cp_wait<1>(); else cp_wait<0>();
        __syncthreads();

        __half* sA = sm + (size_t)(kt & 1) * (BM + BN) * SKA;
        __half* sB = sA + BM * SKA;
#pragma unroll
        for (int kk = 0; kk < BK; kk += 16) {
            wmma::fragment<wmma::matrix_a, 16, 16, 16, __half, wmma::row_major> af[4];
            wmma::fragment<wmma::matrix_b, 16, 16, 16, __half, wmma::col_major> bf[2];
#pragma unroll
            for (int i = 0; i < 4; i++)
                wmma::load_matrix_sync(af[i], sA + (wm * 64 + i * 16) * SKA + kk, SKA);
#pragma unroll
            for (int j = 0; j < 2; j++)
                wmma::load_matrix_sync(bf[j], sB + (wn * 32 + j * 16) * SKA + kk, SKA);
#pragma unroll
            for (int i = 0; i < 4; i++)
#pragma unroll
                for (int j = 0; j < 2; j++)
                    wmma::mma_sync(acc[i][j], af[i], bf[j], acc[i][j]);
        }
        __syncthreads();
        if (kt + 2 < NKt) load_stage(kt & 1, (kt + 2) * BK);
    }

#pragma unroll
    for (int i = 0; i < 4; i++)
#pragma unroll
        for (int j = 0; j < 2; j++)
            wmma::store_matrix_sync(C + (size_t)(m0 + wm * 64 + i * 16) * N
                                      + n0 + wn * 32 + j * 16,
                                    acc[i][j], N, wmma::mem_row_major);
}

// ---------------- FA2-style flash attention: register-resident everything ----------------
// TQ=128 (8 warps x 16 q-rows), TK=64, 4-stage cp.async K/V ring, 1 sync/tile.
#define TQA 128
#define TKA 64
#define SQL 136                      // half stride, 272B rows
#define NSTG 4
#define ATTN_SMEM ((TQA*SQL + 2*NSTG*TKA*SQL)*2)   // 174080 B

__global__ void __launch_bounds__(256) attn_kernel()
{
    extern __shared__ __align__(16) char smem_raw[];
    __half* sQ = (__half*)smem_raw;              // 128 x SQL
    __half* sK = sQ + TQA * SQL;                 // 4 stages x 64 x SQL
    __half* sV = sK + NSTG * TKA * SQL;          // 4 stages x 64 x SQL

    const int tid = threadIdx.x;
    const int w = tid >> 5, l = tid & 31;
    const int q0 = blockIdx.x * TQA;
    const int bh = blockIdx.y;
    const int b = bh / NH, h = bh % NH;
    const int kvh = h / (NH / NKV);

    const __half* Qg = g_Q + ((size_t)bh * SEQ + q0) * HD;
    const __half* Kg = g_K + ((size_t)(b * NKV + kvh) * SEQ) * HD;
    const __half* Vg = g_V + ((size_t)(b * NKV + kvh) * SEQ) * HD;
    const int NT = SEQ / TKA;   // 32

    // prologue: Q (own group)
#pragma unroll
    for (int i = 0; i < 8; i++) {
        int u = tid + i * 256;
        int r = u >> 4, c = (u & 15) * 8;
        cp_async16(sQ + r * SQL + c, Qg + r * HD + c);
    }
    cp_commit();

    auto loadKV = [&](int t) {
        const __half* ks = Kg + (size_t)t * TKA * HD;
        const __half* vs = Vg + (size_t)t * TKA * HD;
        __half* kd = sK + (size_t)(t & (NSTG - 1)) * TKA * SQL;
        __half* vd = sV + (size_t)(t & (NSTG - 1)) * TKA * SQL;
#pragma unroll
        for (int i = 0; i < 4; i++) {
            int u = tid + i * 256;
            int r = u >> 4, c = (u & 15) * 8;
            cp_async16(kd + r * SQL + c, ks + r * HD + c);
            cp_async16(vd + r * SQL + c, vs + r * HD + c);
        }
        cp_commit();
    };
    loadKV(0); loadKV(1); loadKV(2);

    cp_wait<3>();            // Q complete (oldest of 4 groups)
    __syncthreads();

    // Q fragments to registers (8 d-chunks x 4 regs)
    uint32_t qa[8][4];
    {
        int qrow = w * 16 + (l & 15);
        int coff = (l >> 4) * 8;
#pragma unroll
        for (int dc = 0; dc < 8; dc++)
            ldsm_x4(smaddr(sQ + qrow * SQL + dc * 16 + coff),
                    qa[dc][0], qa[dc][1], qa[dc][2], qa[dc][3]);
    }

    float o[16][4];
#pragma unroll
    for (int j = 0; j < 16; j++)
#pragma unroll
        for (int i = 0; i < 4; i++) o[j][i] = 0.0f;
    float m0 = -1e30f, m1 = -1e30f, l0 = 0.0f, l1 = 0.0f;

    const int krow = (l & 7) + ((l >> 4) << 3);      // K ldsm lane row
    const int kcol = ((l >> 3) & 1) * 8;             // K ldsm lane col offset
    const int vrow = (l & 7) + (((l >> 3) & 1) << 3);// V ldsm lane row
    const int vcol = (l >> 4) * 8;                   // V ldsm lane col offset

    for (int kt = 0; kt < NT; kt++) {
        if (kt < NT - 2) cp_wait<2>();
        else if (kt == NT - 2) cp_wait<1>();
        else cp_wait<0>();
        __syncthreads();
        if (kt + 3 < NT) loadKV(kt + 3);

        const __half* Kt = sK + (size_t)(kt & (NSTG - 1)) * TKA * SQL;
        const __half* Vt = sV + (size_t)(kt & (NSTG - 1)) * TKA * SQL;

        // S = Q @ K^T : 8 n-tiles (64 kpos) x 8 d-chunks
        float s[8][4];
#pragma unroll
        for (int j = 0; j < 8; j++)
#pragma unroll
            for (int i = 0; i < 4; i++) s[j][i] = 0.0f;
#pragma unroll
        for (int dc = 0; dc < 8; dc++) {
#pragma unroll
            for (int np = 0; np < 4; np++) {
                uint32_t b0, b1, b2, b3;
                ldsm_x4(smaddr(Kt + (np * 16 + krow) * SQL + dc * 16 + kcol),
                        b0, b1, b2, b3);
                mma16816(s[2 * np],     qa[dc], b0, b1);
                mma16816(s[2 * np + 1], qa[dc], b2, b3);
            }
        }

        // online softmax, fully in registers
        float mx0 = -1e30f, mx1 = -1e30f;
#pragma unroll
        for (int j = 0; j < 8; j++) {
            mx0 = fmaxf(mx0, fmaxf(s[j][0], s[j][1]));
            mx1 = fmaxf(mx1, fmaxf(s[j][2], s[j][3]));
        }
        mx0 = fmaxf(mx0, __shfl_xor_sync(0xffffffffu, mx0, 1));
        mx0 = fmaxf(mx0, __shfl_xor_sync(0xffffffffu, mx0, 2));
        mx1 = fmaxf(mx1, __shfl_xor_sync(0xffffffffu, mx1, 1));
        mx1 = fmaxf(mx1, __shfl_xor_sync(0xffffffffu, mx1, 2));
        float mn0 = fmaxf(m0, mx0), mn1 = fmaxf(m1, mx1);
        float f0 = __expf(m0 - mn0), f1 = __expf(m1 - mn1);
        m0 = mn0; m1 = mn1;
        float sum0 = 0.0f, sum1 = 0.0f;
#pragma unroll
        for (int j = 0; j < 8; j++) {
            s[j][0] = __expf(s[j][0] - mn0);
            s[j][1] = __expf(s[j][1] - mn0);
            s[j][2] = __expf(s[j][2] - mn1);
            s[j][3] = __expf(s[j][3] - mn1);
            sum0 += s[j][0] + s[j][1];
            sum1 += s[j][2] + s[j][3];
        }
        sum0 += __shfl_xor_sync(0xffffffffu, sum0, 1);
        sum0 += __shfl_xor_sync(0xffffffffu, sum0, 2);
        sum1 += __shfl_xor_sync(0xffffffffu, sum1, 1);
        sum1 += __shfl_xor_sync(0xffffffffu, sum1, 2);
        l0 = l0 * f0 + sum0;
        l1 = l1 * f1 + sum1;
#pragma unroll
        for (int j = 0; j < 16; j++) {
            o[j][0] *= f0; o[j][1] *= f0;
            o[j][2] *= f1; o[j][3] *= f1;
        }

        // O += P @ V : 4 kpos-chunks x 8 d n-tile-pairs; P from S regs
#pragma unroll
        for (int t = 0; t < 4; t++) {
            uint32_t pa[4];
            pa[0] = h2pack(s[2 * t][0],     s[2 * t][1]);
            pa[1] = h2pack(s[2 * t][2],     s[2 * t][3]);
            pa[2] = h2pack(s[2 * t + 1][0], s[2 * t + 1][1]);
            pa[3] = h2pack(s[2 * t + 1][2], s[2 * t + 1][3]);
#pragma unroll
            for (int npp = 0; npp < 8; npp++) {
                uint32_t b0, b1, b2, b3;
                ldsm_x4_t(smaddr(Vt + (t * 16 + vrow) * SQL + npp * 16 + vcol),
                          b0, b1, b2, b3);
                mma16816(o[2 * npp],     pa, b0, b1);
                mma16816(o[2 * npp + 1], pa, b2, b3);
            }
        }
    }

    // epilogue: normalize, write half2 directly to g_attn
    float inv0 = 1.0f / l0, inv1 = 1.0f / l1;
    int grow = b * SEQ + q0 + w * 16 + (l >> 2);
    __half* O0 = g_attn + (size_t)grow * (NH * HD) + h * HD;
    __half* O1 = O0 + (size_t)8 * (NH * HD);
#pragma unroll
    for (int j = 0; j < 16; j++) {
        int col = j * 8 + 2 * (l & 3);
        *(__half2*)(O0 + col) = __floats2half2_rn(o[j][0] * inv0, o[j][1] * inv0);
        *(__half2*)(O1 + col) = __floats2half2_rn(o[j][2] * inv1, o[j][3] * inv1);
    }
}

// ---------------- launch ----------------
extern "C" void kernel_launch(void* const* d_in, const int* in_sizes, int n_in,
                              void* d_out, int out_size)
{
    const float* hidden = (const float*)d_in[0];
    const float* Wq = (const float*)d_in[1];
    const float* Wk = (const float*)d_in[2];
    const float* Wv = (const float*)d_in[3];
    const float* Wo = (const float*)d_in[4];
    float* out = (float*)d_out;

    cudaFuncSetAttribute(attn_kernel, cudaFuncAttributeMaxDynamicSharedMemorySize, ATTN_SMEM);
    cudaFuncSetAttribute(gemm_tn, cudaFuncAttributeMaxDynamicSharedMemorySize, GEMM_SMEM);

    __half *p_hX, *p_Wq, *p_Wkv, *p_Wo, *p_Q, *p_K, *p_V, *p_attn;
    float *p_qf, *p_kvf;
    cudaGetSymbolAddress((void**)&p_hX,  g_hX);
    cudaGetSymbolAddress((void**)&p_Wq,  g_Wq);
    cudaGetSymbolAddress((void**)&p_Wkv, g_Wkv);
    cudaGetSymbolAddress((void**)&p_Wo,  g_Wo);
    cudaGetSymbolAddress((void**)&p_attn, g_attn);
    cudaGetSymbolAddress((void**)&p_qf,  g_qf);
    cudaGetSymbolAddress((void**)&p_kvf, g_kvf);
    cudaGetSymbolAddress((void**)&p_Q, g_Q);
    cudaGetSymbolAddress((void**)&p_K, g_K);
    cudaGetSymbolAddress((void**)&p_V, g_V);

    const int T = 256;
    f2h4_kernel<<<(MROWS*HID/4 + T-1)/T, T>>>((const float4*)hidden, p_hX, MROWS*HID/4);
    f2h4_kernel<<<(NH*HD*HID/4 + T-1)/T, T>>>((const float4*)Wq, p_Wq, NH*HD*HID/4);
    f2h4_kernel<<<(NKV*HD*HID/4 + T-1)/T, T>>>((const float4*)Wk, p_Wkv, NKV*HD*HID/4);
    f2h4_kernel<<<(NKV*HD*HID/4 + T-1)/T, T>>>((const float4*)Wv, p_Wkv + (size_t)NKV*HD*HID, NKV*HD*HID/4);
    f2h4_kernel<<<(HID*NH*HD/4 + T-1)/T, T>>>((const float4*)Wo, p_Wo, HID*NH*HD/4);

    tab_kernel<<<(SEQ*64 + T-1)/T, T>>>();

    gemm_tn<<<dim3((NH*HD)/BN,  MROWS/BM), T, GEMM_SMEM>>>(p_hX, p_Wq,  p_qf,  MROWS, NH*HD,    HID);
    gemm_tn<<<dim3((2*NKV*HD)/BN, MROWS/BM), T, GEMM_SMEM>>>(p_hX, p_Wkv, p_kvf, MROWS, 2*NKV*HD, HID);

    const float qscale = 0.08838834764831845f;
    rope_kernel<<<(BB*SEQ*NH*64 + T-1)/T, T>>>(p_qf, p_Q, NH, NH*HD, qscale);
    rope_kernel<<<(BB*SEQ*NKV*64 + T-1)/T, T>>>(p_kvf, p_K, NKV, 2*NKV*HD, 1.0f);
    vtrans_kernel<<<(BB*SEQ*NKV*HD + T-1)/T, T>>>(p_kvf, p_V);

    attn_kernel<<<dim3(SEQ/TQA, BB*NH), T, ATTN_SMEM>>>();

    gemm_tn<<<dim3(HID/BN, MROWS/BM), T, GEMM_SMEM>>>(p_attn, p_Wo, out, MROWS, HID, NH*HD);
}

// round 7
// speedup vs baseline: 2.0160x; 1.0464x over previous
#include <cuda_runtime.h>
#include <cuda_fp16.h>
#include <math.h>
#include <stdint.h>
#include <cstdint>

#define NH   16
#define NKV  4
#define HD   128
#define BB   2
#define SEQ  2048
#define HID  2048
#define MROWS (BB*SEQ)

// ---------------- device scratch ----------------
__device__ __half g_hX [MROWS*HID];
__device__ __half g_Wq [NH*HD*HID];
__device__ __half g_Wkv[(2*NKV*HD)*HID];
__device__ __half g_Wo [HID*NH*HD];
__device__ float  g_qf [MROWS*NH*HD];
__device__ float  g_kvf[MROWS*2*NKV*HD];
__device__ __half g_Q  [BB*NH*SEQ*HD];
__device__ __half g_K  [BB*NKV*SEQ*HD];
__device__ __half g_V  [BB*NKV*SEQ*HD];
__device__ __half g_attn[MROWS*NH*HD];
__device__ float  g_cos[SEQ*64];
__device__ float  g_sin[SEQ*64];

// ---------------- cp.async helpers ----------------
__device__ __forceinline__ void cp_async16(void* smem, const void* gmem)
{
    unsigned s = (unsigned)__cvta_generic_to_shared(smem);
    asm volatile("cp.async.cg.shared.global [%0], [%1], 16;\n" :: "r"(s), "l"(gmem));
}
__device__ __forceinline__ void cp_commit() { asm volatile("cp.async.commit_group;\n"); }
template<int N> __device__ __forceinline__ void cp_wait()
{
    asm volatile("cp.async.wait_group %0;\n" :: "n"(N));
}

// ---------------- mma / ldmatrix primitives ----------------
__device__ __forceinline__ uint32_t smaddr(const void* p)
{
    return (uint32_t)__cvta_generic_to_shared(p);
}
__device__ __forceinline__ void ldsm_x4(uint32_t a, uint32_t& r0, uint32_t& r1,
                                        uint32_t& r2, uint32_t& r3)
{
    asm volatile("ldmatrix.sync.aligned.m8n8.x4.shared.b16 {%0,%1,%2,%3}, [%4];"
                 : "=r"(r0), "=r"(r1), "=r"(r2), "=r"(r3) : "r"(a));
}
__device__ __forceinline__ void ldsm_x4_t(uint32_t a, uint32_t& r0, uint32_t& r1,
                                          uint32_t& r2, uint32_t& r3)
{
    asm volatile("ldmatrix.sync.aligned.m8n8.x4.trans.shared.b16 {%0,%1,%2,%3}, [%4];"
                 : "=r"(r0), "=r"(r1), "=r"(r2), "=r"(r3) : "r"(a));
}
__device__ __forceinline__ void mma16816(float* c, const uint32_t* a, uint32_t b0, uint32_t b1)
{
    asm volatile("mma.sync.aligned.m16n8k16.row.col.f32.f16.f16.f32 "
                 "{%0,%1,%2,%3}, {%4,%5,%6,%7}, {%8,%9}, {%0,%1,%2,%3};"
                 : "+f"(c[0]), "+f"(c[1]), "+f"(c[2]), "+f"(c[3])
                 : "r"(a[0]), "r"(a[1]), "r"(a[2]), "r"(a[3]), "r"(b0), "r"(b1));
}
__device__ __forceinline__ uint32_t h2pack(float x, float y)
{
    __half2 h = __floats2half2_rn(x, y);
    return *(uint32_t*)&h;
}

// ---------------- elementwise: float4 -> half4 ----------------
__global__ void f2h4_kernel(const float4* __restrict__ src, __half* __restrict__ dst, int n4)
{
    int i = blockIdx.x * blockDim.x + threadIdx.x;
    if (i < n4) {
        float4 v = src[i];
        __half2* d = (__half2*)(dst + (size_t)i * 4);
        d[0] = __floats2half2_rn(v.x, v.y);
        d[1] = __floats2half2_rn(v.z, v.w);
    }
}

// ---------------- RoPE table ----------------
__global__ void tab_kernel()
{
    int tid = blockIdx.x * blockDim.x + threadIdx.x;
    if (tid >= SEQ * 64) return;
    int s = tid / 64, i = tid % 64;
    double inv = pow(10000.0, -(double)i / 64.0);
    double ang = (double)s * inv;
    double sn, cs;
    sincos(ang, &sn, &cs);
    g_cos[tid] = (float)cs;
    g_sin[tid] = (float)sn;
}

// ---------------- RoPE + transpose ----------------
__global__ void rope_kernel(const float* __restrict__ lin, __half* __restrict__ dst,
                            int nheads, int rowstride, float scale)
{
    int tid = blockIdx.x * blockDim.x + threadIdx.x;
    int total = BB * SEQ * nheads * 64;
    if (tid >= total) return;
    int i = tid & 63;
    int h = (tid >> 6) % nheads;
    int s = (tid / (64 * nheads)) % SEQ;
    int b = tid / (64 * nheads * SEQ);
    const float* p = lin + (size_t)(b * SEQ + s) * rowstride + h * HD;
    float x1 = p[i], x2 = p[i + 64];
    float c = g_cos[s * 64 + i], sn = g_sin[s * 64 + i];
    __half* o = dst + ((size_t)(b * nheads + h) * SEQ + s) * HD;
    o[i]      = __float2half((x1 * c - x2 * sn) * scale);
    o[i + 64] = __float2half((x2 * c + x1 * sn) * scale);
}

__global__ void vtrans_kernel(const float* __restrict__ lin, __half* __restrict__ dst)
{
    int tid = blockIdx.x * blockDim.x + threadIdx.x;
    int total = BB * SEQ * NKV * HD;
    if (tid >= total) return;
    int d  = tid % HD;
    int t2 = tid / HD;
    int kv = t2 % NKV;
    int t3 = t2 / NKV;
    int s  = t3 % SEQ;
    int b  = t3 / SEQ;
    dst[((size_t)(b * NKV + kv) * SEQ + s) * HD + d] =
        __float2half(lin[(size_t)(b * SEQ + s) * (2 * NKV * HD) + NKV * HD + kv * HD + d]);
}

// ======== Raw-mma TN GEMM: C[M,N] = A[M,K] * B[N,K]^T (fp16 in, fp32 out) ========
// 8 warps as 2(m) x 4(n); warp tile 64x32; BK=64; 3-stage cp.async; 1 sync/iter.
#define GBM 128
#define GBN 128
#define GBK 64
#define GST 72                                  // half stride (144B rows)
#define GNSTG 3
#define GEMM_SMEM (GNSTG*(GBM+GBN)*GST*2)       // 110592 B

__global__ void __launch_bounds__(256, 2) gemm_tn(const __half* __restrict__ A,
                                                  const __half* __restrict__ Bm,
                                                  float* __restrict__ C,
                                                  int M, int N, int K)
{
    extern __shared__ __align__(16) __half sm[];
    const int tid = threadIdx.x;
    const int w = tid >> 5, l = tid & 31;
    const int wm = w >> 2, wn = w & 3;
    const int m0 = blockIdx.y * GBM, n0 = blockIdx.x * GBN;
    const int NT = K / GBK;
    const int stageH = (GBM + GBN) * GST;

    auto loadStage = [&](int t) {
        __half* sA = sm + (size_t)(t % GNSTG) * stageH;
        __half* sB = sA + GBM * GST;
        const __half* Ag = A + (size_t)m0 * K + t * GBK;
        const __half* Bg = Bm + (size_t)n0 * K + t * GBK;
#pragma unroll
        for (int i = 0; i < 4; i++) {
            int u = tid + i * 256;
            int r = u >> 3, c = (u & 7) * 8;
            cp_async16(sA + r * GST + c, Ag + (size_t)r * K + c);
        }
#pragma unroll
        for (int i = 0; i < 4; i++) {
            int u = tid + i * 256;
            int r = u >> 3, c = (u & 7) * 8;
            cp_async16(sB + r * GST + c, Bg + (size_t)r * K + c);
        }
        cp_commit();
    };

    loadStage(0); loadStage(1);

    float acc[4][4][4];
#pragma unroll
    for (int mi = 0; mi < 4; mi++)
#pragma unroll
        for (int nj = 0; nj < 4; nj++)
#pragma unroll
            for (int e = 0; e < 4; e++) acc[mi][nj][e] = 0.0f;

    const int arow_l = (l & 15);
    const int acoff  = (l >> 4) * 8;
    const int krow   = (l & 7) + ((l >> 4) << 3);
    const int kcol   = ((l >> 3) & 1) * 8;

    for (int t = 0; t < NT; t++) {
        if (t < NT - 1) cp_wait<1>(); else cp_wait<0>();
        __syncthreads();
        if (t + 2 < NT) loadStage(t + 2);

        const __half* sA = sm + (size_t)(t % GNSTG) * stageH;
        const __half* sB = sA + GBM * GST;

#pragma unroll
        for (int dc = 0; dc < 4; dc++) {                 // k16 steps
            uint32_t a[4][4];
#pragma unroll
            for (int mi = 0; mi < 4; mi++)
                ldsm_x4(smaddr(sA + (wm * 64 + mi * 16 + arow_l) * GST + dc * 16 + acoff),
                        a[mi][0], a[mi][1], a[mi][2], a[mi][3]);
#pragma unroll
            for (int np = 0; np < 2; np++) {             // 2 x n16
                uint32_t b0, b1, b2, b3;
                ldsm_x4(smaddr(sB + (wn * 32 + np * 16 + krow) * GST + dc * 16 + kcol),
                        b0, b1, b2, b3);
#pragma unroll
                for (int mi = 0; mi < 4; mi++) {
                    mma16816(acc[mi][2 * np],     a[mi], b0, b1);
                    mma16816(acc[mi][2 * np + 1], a[mi], b2, b3);
                }
            }
        }
    }

    // epilogue: float2 stores from registers
#pragma unroll
    for (int mi = 0; mi < 4; mi++) {
        int row = m0 + wm * 64 + mi * 16 + (l >> 2);
        float* C0 = C + (size_t)row * N + n0 + wn * 32;
        float* C1 = C0 + (size_t)8 * N;
#pragma unroll
        for (int nj = 0; nj < 4; nj++) {
            int col = nj * 8 + (l & 3) * 2;
            *(float2*)(C0 + col) = make_float2(acc[mi][nj][0], acc[mi][nj][1]);
            *(float2*)(C1 + col) = make_float2(acc[mi][nj][2], acc[mi][nj][3]);
        }
    }
}

// ---------------- FA2-style flash attention (unchanged from R5) ----------------
#define TQA 128
#define TKA 64
#define SQL 136
#define NSTG 4
#define ATTN_SMEM ((TQA*SQL + 2*NSTG*TKA*SQL)*2)

__global__ void __launch_bounds__(256) attn_kernel()
{
    extern __shared__ __align__(16) char smem_raw[];
    __half* sQ = (__half*)smem_raw;
    __half* sK = sQ + TQA * SQL;
    __half* sV = sK + NSTG * TKA * SQL;

    const int tid = threadIdx.x;
    const int w = tid >> 5, l = tid & 31;
    const int q0 = blockIdx.x * TQA;
    const int bh = blockIdx.y;
    const int b = bh / NH, h = bh % NH;
    const int kvh = h / (NH / NKV);

    const __half* Qg = g_Q + ((size_t)bh * SEQ + q0) * HD;
    const __half* Kg = g_K + ((size_t)(b * NKV + kvh) * SEQ) * HD;
    const __half* Vg = g_V + ((size_t)(b * NKV + kvh) * SEQ) * HD;
    const int NT = SEQ / TKA;

#pragma unroll
    for (int i = 0; i < 8; i++) {
        int u = tid + i * 256;
        int r = u >> 4, c = (u & 15) * 8;
        cp_async16(sQ + r * SQL + c, Qg + r * HD + c);
    }
    cp_commit();

    auto loadKV = [&](int t) {
        const __half* ks = Kg + (size_t)t * TKA * HD;
        const __half* vs = Vg + (size_t)t * TKA * HD;
        __half* kd = sK + (size_t)(t & (NSTG - 1)) * TKA * SQL;
        __half* vd = sV + (size_t)(t & (NSTG - 1)) * TKA * SQL;
#pragma unroll
        for (int i = 0; i < 4; i++) {
            int u = tid + i * 256;
            int r = u >> 4, c = (u & 15) * 8;
            cp_async16(kd + r * SQL + c, ks + r * HD + c);
            cp_async16(vd + r * SQL + c, vs + r * HD + c);
        }
        cp_commit();
    };
    loadKV(0); loadKV(1); loadKV(2);

    cp_wait<3>();
    __syncthreads();

    uint32_t qa[8][4];
    {
        int qrow = w * 16 + (l & 15);
        int coff = (l >> 4) * 8;
#pragma unroll
        for (int dc = 0; dc < 8; dc++)
            ldsm_x4(smaddr(sQ + qrow * SQL + dc * 16 + coff),
                    qa[dc][0], qa[dc][1], qa[dc][2], qa[dc][3]);
    }

    float o[16][4];
#pragma unroll
    for (int j = 0; j < 16; j++)
#pragma unroll
        for (int i = 0; i < 4; i++) o[j][i] = 0.0f;
    float m0 = -1e30f, m1 = -1e30f, l0 = 0.0f, l1 = 0.0f;

    const int krow = (l & 7) + ((l >> 4) << 3);
    const int kcol = ((l >> 3) & 1) * 8;
    const int vrow = (l & 7) + (((l >> 3) & 1) << 3);
    const int vcol = (l >> 4) * 8;

    for (int kt = 0; kt < NT; kt++) {
        if (kt < NT - 2) cp_wait<2>();
        else if (kt == NT - 2) cp_wait<1>();
        else cp_wait<0>();
        __syncthreads();
        if (kt + 3 < NT) loadKV(kt + 3);

        const __half* Kt = sK + (size_t)(kt & (NSTG - 1)) * TKA * SQL;
        const __half* Vt = sV + (size_t)(kt & (NSTG - 1)) * TKA * SQL;

        float s[8][4];
#pragma unroll
        for (int j = 0; j < 8; j++)
#pragma unroll
            for (int i = 0; i < 4; i++) s[j][i] = 0.0f;
#pragma unroll
        for (int dc = 0; dc < 8; dc++) {
#pragma unroll
            for (int np = 0; np < 4; np++) {
                uint32_t b0, b1, b2, b3;
                ldsm_x4(smaddr(Kt + (np * 16 + krow) * SQL + dc * 16 + kcol),
                        b0, b1, b2, b3);
                mma16816(s[2 * np],     qa[dc], b0, b1);
                mma16816(s[2 * np + 1], qa[dc], b2, b3);
            }
        }

        float mx0 = -1e30f, mx1 = -1e30f;
#pragma unroll
        for (int j = 0; j < 8; j++) {
            mx0 = fmaxf(mx0, fmaxf(s[j][0], s[j][1]));
            mx1 = fmaxf(mx1, fmaxf(s[j][2], s[j][3]));
        }
        mx0 = fmaxf(mx0, __shfl_xor_sync(0xffffffffu, mx0, 1));
        mx0 = fmaxf(mx0, __shfl_xor_sync(0xffffffffu, mx0, 2));
        mx1 = fmaxf(mx1, __shfl_xor_sync(0xffffffffu, mx1, 1));
        mx1 = fmaxf(mx1, __shfl_xor_sync(0xffffffffu, mx1, 2));
        float mn0 = fmaxf(m0, mx0), mn1 = fmaxf(m1, mx1);
        float f0 = __expf(m0 - mn0), f1 = __expf(m1 - mn1);
        m0 = mn0; m1 = mn1;
        float sum0 = 0.0f, sum1 = 0.0f;
#pragma unroll
        for (int j = 0; j < 8; j++) {
            s[j][0] = __expf(s[j][0] - mn0);
            s[j][1] = __expf(s[j][1] - mn0);
            s[j][2] = __expf(s[j][2] - mn1);
            s[j][3] = __expf(s[j][3] - mn1);
            sum0 += s[j][0] + s[j][1];
            sum1 += s[j][2] + s[j][3];
        }
        sum0 += __shfl_xor_sync(0xffffffffu, sum0, 1);
        sum0 += __shfl_xor_sync(0xffffffffu, sum0, 2);
        sum1 += __shfl_xor_sync(0xffffffffu, sum1, 1);
        sum1 += __shfl_xor_sync(0xffffffffu, sum1, 2);
        l0 = l0 * f0 + sum0;
        l1 = l1 * f1 + sum1;
#pragma unroll
        for (int j = 0; j < 16; j++) {
            o[j][0] *= f0; o[j][1] *= f0;
            o[j][2] *= f1; o[j][3] *= f1;
        }

#pragma unroll
        for (int t = 0; t < 4; t++) {
            uint32_t pa[4];
            pa[0] = h2pack(s[2 * t][0],     s[2 * t][1]);
            pa[1] = h2pack(s[2 * t][2],     s[2 * t][3]);
            pa[2] = h2pack(s[2 * t + 1][0], s[2 * t + 1][1]);
            pa[3] = h2pack(s[2 * t + 1][2], s[2 * t + 1][3]);
#pragma unroll
            for (int npp = 0; npp < 8; npp++) {
                uint32_t b0, b1, b2, b3;
                ldsm_x4_t(smaddr(Vt + (t * 16 + vrow) * SQL + npp * 16 + vcol),
                          b0, b1, b2, b3);
                mma16816(o[2 * npp],     pa, b0, b1);
                mma16816(o[2 * npp + 1], pa, b2, b3);
            }
        }
    }

    float inv0 = 1.0f / l0, inv1 = 1.0f / l1;
    int grow = b * SEQ + q0 + w * 16 + (l >> 2);
    __half* O0 = g_attn + (size_t)grow * (NH * HD) + h * HD;
    __half* O1 = O0 + (size_t)8 * (NH * HD);
#pragma unroll
    for (int j = 0; j < 16; j++) {
        int col = j * 8 + 2 * (l & 3);
        *(__half2*)(O0 + col) = __floats2half2_rn(o[j][0] * inv0, o[j][1] * inv0);
        *(__half2*)(O1 + col) = __floats2half2_rn(o[j][2] * inv1, o[j][3] * inv1);
    }
}

// ---------------- launch ----------------
extern "C" void kernel_launch(void* const* d_in, const int* in_sizes, int n_in,
                              void* d_out, int out_size)
{
    const float* hidden = (const float*)d_in[0];
    const float* Wq = (const float*)d_in[1];
    const float* Wk = (const float*)d_in[2];
    const float* Wv = (const float*)d_in[3];
    const float* Wo = (const float*)d_in[4];
    float* out = (float*)d_out;

    cudaFuncSetAttribute(attn_kernel, cudaFuncAttributeMaxDynamicSharedMemorySize, ATTN_SMEM);
    cudaFuncSetAttribute(gemm_tn, cudaFuncAttributeMaxDynamicSharedMemorySize, GEMM_SMEM);

    __half *p_hX, *p_Wq, *p_Wkv, *p_Wo, *p_Q, *p_K, *p_V, *p_attn;
    float *p_qf, *p_kvf;
    cudaGetSymbolAddress((void**)&p_hX,  g_hX);
    cudaGetSymbolAddress((void**)&p_Wq,  g_Wq);
    cudaGetSymbolAddress((void**)&p_Wkv, g_Wkv);
    cudaGetSymbolAddress((void**)&p_Wo,  g_Wo);
    cudaGetSymbolAddress((void**)&p_attn, g_attn);
    cudaGetSymbolAddress((void**)&p_qf,  g_qf);
    cudaGetSymbolAddress((void**)&p_kvf, g_kvf);
    cudaGetSymbolAddress((void**)&p_Q, g_Q);
    cudaGetSymbolAddress((void**)&p_K, g_K);
    cudaGetSymbolAddress((void**)&p_V, g_V);

    const int T = 256;
    f2h4_kernel<<<(MROWS*HID/4 + T-1)/T, T>>>((const float4*)hidden, p_hX, MROWS*HID/4);
    f2h4_kernel<<<(NH*HD*HID/4 + T-1)/T, T>>>((const float4*)Wq, p_Wq, NH*HD*HID/4);
    f2h4_kernel<<<(NKV*HD*HID/4 + T-1)/T, T>>>((const float4*)Wk, p_Wkv, NKV*HD*HID/4);
    f2h4_kernel<<<(NKV*HD*HID/4 + T-1)/T, T>>>((const float4*)Wv, p_Wkv + (size_t)NKV*HD*HID, NKV*HD*HID/4);
    f2h4_kernel<<<(HID*NH*HD/4 + T-1)/T, T>>>((const float4*)Wo, p_Wo, HID*NH*HD/4);

    tab_kernel<<<(SEQ*64 + T-1)/T, T>>>();

    gemm_tn<<<dim3((NH*HD)/GBN,    MROWS/GBM), T, GEMM_SMEM>>>(p_hX, p_Wq,  p_qf,  MROWS, NH*HD,    HID);
    gemm_tn<<<dim3((2*NKV*HD)/GBN, MROWS/GBM), T, GEMM_SMEM>>>(p_hX, p_Wkv, p_kvf, MROWS, 2*NKV*HD, HID);

    const float qscale = 0.08838834764831845f;
    rope_kernel<<<(BB*SEQ*NH*64 + T-1)/T, T>>>(p_qf, p_Q, NH, NH*HD, qscale);
    rope_kernel<<<(BB*SEQ*NKV*64 + T-1)/T, T>>>(p_kvf, p_K, NKV, 2*NKV*HD, 1.0f);
    vtrans_kernel<<<(BB*SEQ*NKV*HD + T-1)/T, T>>>(p_kvf, p_V);

    attn_kernel<<<dim3(SEQ/TQA, BB*NH), T, ATTN_SMEM>>>();

    gemm_tn<<<dim3(HID/GBN, MROWS/GBM), T, GEMM_SMEM>>>(p_attn, p_Wo, out, MROWS, HID, NH*HD);
}

// round 8
// speedup vs baseline: 2.0296x; 1.0067x over previous
#include <cuda_runtime.h>
#include <cuda_fp16.h>
#include <math.h>
#include <stdint.h>
#include <cstdint>

#define NH   16
#define NKV  4
#define HD   128
#define BB   2
#define SEQ  2048
#define HID  2048
#define MROWS (BB*SEQ)

// scale folded into Q: (1/sqrt(128)) * log2(e)
#define QSCL 0.1275174337f

// ---------------- device scratch ----------------
__device__ __half g_hX [MROWS*HID];
__device__ __half g_Wq [NH*HD*HID];
__device__ __half g_Wkv[(2*NKV*HD)*HID];
__device__ __half g_Wo [HID*NH*HD];
__device__ __half g_Q  [BB*NH*SEQ*HD];     // roped, pre-scaled by QSCL
__device__ __half g_K  [BB*NKV*SEQ*HD];    // roped
__device__ __half g_V  [BB*NKV*SEQ*HD];
__device__ __half g_attn[MROWS*NH*HD];
__device__ float  g_cos[SEQ*64];
__device__ float  g_sin[SEQ*64];

// ---------------- cp.async helpers ----------------
__device__ __forceinline__ void cp_async16(void* smem, const void* gmem)
{
    unsigned s = (unsigned)__cvta_generic_to_shared(smem);
    asm volatile("cp.async.cg.shared.global [%0], [%1], 16;\n" :: "r"(s), "l"(gmem));
}
__device__ __forceinline__ void cp_commit() { asm volatile("cp.async.commit_group;\n"); }
template<int N> __device__ __forceinline__ void cp_wait()
{
    asm volatile("cp.async.wait_group %0;\n" :: "n"(N));
}

// ---------------- mma / ldmatrix primitives ----------------
__device__ __forceinline__ uint32_t smaddr(const void* p)
{
    return (uint32_t)__cvta_generic_to_shared(p);
}
__device__ __forceinline__ void ldsm_x4(uint32_t a, uint32_t& r0, uint32_t& r1,
                                        uint32_t& r2, uint32_t& r3)
{
    asm volatile("ldmatrix.sync.aligned.m8n8.x4.shared.b16 {%0,%1,%2,%3}, [%4];"
                 : "=r"(r0), "=r"(r1), "=r"(r2), "=r"(r3) : "r"(a));
}
__device__ __forceinline__ void ldsm_x4_t(uint32_t a, uint32_t& r0, uint32_t& r1,
                                          uint32_t& r2, uint32_t& r3)
{
    asm volatile("ldmatrix.sync.aligned.m8n8.x4.trans.shared.b16 {%0,%1,%2,%3}, [%4];"
                 : "=r"(r0), "=r"(r1), "=r"(r2), "=r"(r3) : "r"(a));
}
__device__ __forceinline__ void mma16816(float* c, const uint32_t* a, uint32_t b0, uint32_t b1)
{
    asm volatile("mma.sync.aligned.m16n8k16.row.col.f32.f16.f16.f32 "
                 "{%0,%1,%2,%3}, {%4,%5,%6,%7}, {%8,%9}, {%0,%1,%2,%3};"
                 : "+f"(c[0]), "+f"(c[1]), "+f"(c[2]), "+f"(c[3])
                 : "r"(a[0]), "r"(a[1]), "r"(a[2]), "r"(a[3]), "r"(b0), "r"(b1));
}
__device__ __forceinline__ uint32_t h2pack(float x, float y)
{
    __half2 h = __floats2half2_rn(x, y);
    return *(uint32_t*)&h;
}

// ---------------- elementwise: float4 -> half4 ----------------
__global__ void f2h4_kernel(const float4* __restrict__ src, __half* __restrict__ dst, int n4)
{
    int i = blockIdx.x * blockDim.x + threadIdx.x;
    if (i < n4) {
        float4 v = src[i];
        __half2* d = (__half2*)(dst + (size_t)i * 4);
        d[0] = __floats2half2_rn(v.x, v.y);
        d[1] = __floats2half2_rn(v.z, v.w);
    }
}

// ---------------- RoPE table ----------------
__global__ void tab_kernel()
{
    int tid = blockIdx.x * blockDim.x + threadIdx.x;
    if (tid >= SEQ * 64) return;
    int s = tid / 64, i = tid % 64;
    double inv = pow(10000.0, -(double)i / 64.0);
    double ang = (double)s * inv;
    double sn, cs;
    sincos(ang, &sn, &cs);
    g_cos[tid] = (float)cs;
    g_sin[tid] = (float)sn;
}

// ======== Raw-mma TN GEMM with fused epilogues ========
// C[M,N] = A[M,K] * B[N,K]^T. 8 warps 2x4; warp tile 64x32; BK=64; 3 stages.
// mode 0: plain fp32 C output
// mode 1: Q projection -> rope(*QSCL) -> half to hK ([b,h,s,d], h=blockIdx.x)
// mode 2: KV projection -> bx<4: rope K -> hK; bx>=4: plain V -> hV
#define GBM 128
#define GBN 128
#define GBK 64
#define GST 72
#define GNSTG 3
#define GEMM_SMEM (GNSTG*(GBM+GBN)*GST*2)    // 110592 B
#define EST 132                              // fp32 epilogue stride

__global__ void __launch_bounds__(256, 2) gemm_tn(const __half* __restrict__ A,
                                                  const __half* __restrict__ Bm,
                                                  float* __restrict__ C,
                                                  __half* __restrict__ hK,
                                                  __half* __restrict__ hV,
                                                  int M, int N, int K, int mode)
{
    extern __shared__ __align__(16) __half sm[];
    const int tid = threadIdx.x;
    const int w = tid >> 5, l = tid & 31;
    const int wm = w >> 2, wn = w & 3;
    const int m0 = blockIdx.y * GBM, n0 = blockIdx.x * GBN;
    const int NT = K / GBK;
    const int stageH = (GBM + GBN) * GST;

    auto loadStage = [&](int t) {
        __half* sA = sm + (size_t)(t % GNSTG) * stageH;
        __half* sB = sA + GBM * GST;
        const __half* Ag = A + (size_t)m0 * K + t * GBK;
        const __half* Bg = Bm + (size_t)n0 * K + t * GBK;
#pragma unroll
        for (int i = 0; i < 4; i++) {
            int u = tid + i * 256;
            int r = u >> 3, c = (u & 7) * 8;
            cp_async16(sA + r * GST + c, Ag + (size_t)r * K + c);
        }
#pragma unroll
        for (int i = 0; i < 4; i++) {
            int u = tid + i * 256;
            int r = u >> 3, c = (u & 7) * 8;
            cp_async16(sB + r * GST + c, Bg + (size_t)r * K + c);
        }
        cp_commit();
    };

    loadStage(0); loadStage(1);

    float acc[4][4][4];
#pragma unroll
    for (int mi = 0; mi < 4; mi++)
#pragma unroll
        for (int nj = 0; nj < 4; nj++)
#pragma unroll
            for (int e = 0; e < 4; e++) acc[mi][nj][e] = 0.0f;

    const int arow_l = (l & 15);
    const int acoff  = (l >> 4) * 8;
    const int krow   = (l & 7) + ((l >> 4) << 3);
    const int kcol   = ((l >> 3) & 1) * 8;

    for (int t = 0; t < NT; t++) {
        if (t < NT - 1) cp_wait<1>(); else cp_wait<0>();
        __syncthreads();
        if (t + 2 < NT) loadStage(t + 2);

        const __half* sA = sm + (size_t)(t % GNSTG) * stageH;
        const __half* sB = sA + GBM * GST;

#pragma unroll
        for (int dc = 0; dc < 4; dc++) {
            uint32_t a[4][4];
#pragma unroll
            for (int mi = 0; mi < 4; mi++)
                ldsm_x4(smaddr(sA + (wm * 64 + mi * 16 + arow_l) * GST + dc * 16 + acoff),
                        a[mi][0], a[mi][1], a[mi][2], a[mi][3]);
#pragma unroll
            for (int np = 0; np < 2; np++) {
                uint32_t b0, b1, b2, b3;
                ldsm_x4(smaddr(sB + (wn * 32 + np * 16 + krow) * GST + dc * 16 + kcol),
                        b0, b1, b2, b3);
#pragma unroll
                for (int mi = 0; mi < 4; mi++) {
                    mma16816(acc[mi][2 * np],     a[mi], b0, b1);
                    mma16816(acc[mi][2 * np + 1], a[mi], b2, b3);
                }
            }
        }
    }

    if (mode == 0) {
        // plain fp32 epilogue
#pragma unroll
        for (int mi = 0; mi < 4; mi++) {
            int row = m0 + wm * 64 + mi * 16 + (l >> 2);
            float* C0 = C + (size_t)row * N + n0 + wn * 32;
            float* C1 = C0 + (size_t)8 * N;
#pragma unroll
            for (int nj = 0; nj < 4; nj++) {
                int col = nj * 8 + (l & 3) * 2;
                *(float2*)(C0 + col) = make_float2(acc[mi][nj][0], acc[mi][nj][1]);
                *(float2*)(C1 + col) = make_float2(acc[mi][nj][2], acc[mi][nj][3]);
            }
        }
        return;
    }

    // fused rope / convert epilogue: stage accs through smem fp32
    __syncthreads();                          // all warps done reading stages
    float* sC = (float*)sm;
#pragma unroll
    for (int mi = 0; mi < 4; mi++) {
        int r0 = wm * 64 + mi * 16 + (l >> 2);
#pragma unroll
        for (int nj = 0; nj < 4; nj++) {
            int c0 = wn * 32 + nj * 8 + (l & 3) * 2;
            sC[r0 * EST + c0]           = acc[mi][nj][0];
            sC[r0 * EST + c0 + 1]       = acc[mi][nj][1];
            sC[(r0 + 8) * EST + c0]     = acc[mi][nj][2];
            sC[(r0 + 8) * EST + c0 + 1] = acc[mi][nj][3];
        }
    }
    __syncthreads();

    const int bq = m0 / SEQ;
    const int sbase = m0 % SEQ;

    bool do_rope;
    float scl;
    __half* dst;
    if (mode == 1) {                          // Q head
        do_rope = true; scl = QSCL;
        dst = hK + ((size_t)(bq * NH + blockIdx.x) * SEQ) * HD;
    } else if (blockIdx.x < NKV) {            // K head
        do_rope = true; scl = 1.0f;
        dst = hK + ((size_t)(bq * NKV + blockIdx.x) * SEQ) * HD;
    } else {                                  // V head
        do_rope = false; scl = 1.0f;
        dst = hV + ((size_t)(bq * NKV + (blockIdx.x - NKV)) * SEQ) * HD;
    }

    if (do_rope) {
#pragma unroll
        for (int i = 0; i < 32; i++) {
            int u = tid + i * 256;
            int r = u >> 6, c = u & 63;
            float x1 = sC[r * EST + c], x2 = sC[r * EST + c + 64];
            int s = sbase + r;
            float cs = g_cos[s * 64 + c], sn = g_sin[s * 64 + c];
            dst[(size_t)s * HD + c]      = __float2half((x1 * cs - x2 * sn) * scl);
            dst[(size_t)s * HD + c + 64] = __float2half((x2 * cs + x1 * sn) * scl);
        }
    } else {
#pragma unroll
        for (int i = 0; i < 64; i++) {
            int u = tid + i * 256;
            int r = u >> 7, c = u & 127;
            dst[(size_t)(sbase + r) * HD + c] = __float2half(sC[r * EST + c]);
        }
    }
}

// ---------------- FA2-style flash attention (exp2 domain, lazy rescale) ----------------
#define TQA 128
#define TKA 64
#define SQL 136
#define NSTG 4
#define ATTN_SMEM ((TQA*SQL + 2*NSTG*TKA*SQL)*2)

__global__ void __launch_bounds__(256) attn_kernel()
{
    extern __shared__ __align__(16) char smem_raw[];
    __half* sQ = (__half*)smem_raw;
    __half* sK = sQ + TQA * SQL;
    __half* sV = sK + NSTG * TKA * SQL;

    const int tid = threadIdx.x;
    const int w = tid >> 5, l = tid & 31;
    const int q0 = blockIdx.x * TQA;
    const int bh = blockIdx.y;
    const int b = bh / NH, h = bh % NH;
    const int kvh = h / (NH / NKV);

    const __half* Qg = g_Q + ((size_t)bh * SEQ + q0) * HD;
    const __half* Kg = g_K + ((size_t)(b * NKV + kvh) * SEQ) * HD;
    const __half* Vg = g_V + ((size_t)(b * NKV + kvh) * SEQ) * HD;
    const int NT = SEQ / TKA;

#pragma unroll
    for (int i = 0; i < 8; i++) {
        int u = tid + i * 256;
        int r = u >> 4, c = (u & 15) * 8;
        cp_async16(sQ + r * SQL + c, Qg + r * HD + c);
    }
    cp_commit();

    auto loadKV = [&](int t) {
        const __half* ks = Kg + (size_t)t * TKA * HD;
        const __half* vs = Vg + (size_t)t * TKA * HD;
        __half* kd = sK + (size_t)(t & (NSTG - 1)) * TKA * SQL;
        __half* vd = sV + (size_t)(t & (NSTG - 1)) * TKA * SQL;
#pragma unroll
        for (int i = 0; i < 4; i++) {
            int u = tid + i * 256;
            int r = u >> 4, c = (u & 15) * 8;
            cp_async16(kd + r * SQL + c, ks + r * HD + c);
            cp_async16(vd + r * SQL + c, vs + r * HD + c);
        }
        cp_commit();
    };
    loadKV(0); loadKV(1); loadKV(2);

    cp_wait<3>();
    __syncthreads();

    uint32_t qa[8][4];
    {
        int qrow = w * 16 + (l & 15);
        int coff = (l >> 4) * 8;
#pragma unroll
        for (int dc = 0; dc < 8; dc++)
            ldsm_x4(smaddr(sQ + qrow * SQL + dc * 16 + coff),
                    qa[dc][0], qa[dc][1], qa[dc][2], qa[dc][3]);
    }

    float o[16][4];
#pragma unroll
    for (int j = 0; j < 16; j++)
#pragma unroll
        for (int i = 0; i < 4; i++) o[j][i] = 0.0f;
    float m0 = -1e30f, m1 = -1e30f, l0 = 0.0f, l1 = 0.0f;

    const int krow = (l & 7) + ((l >> 4) << 3);
    const int kcol = ((l >> 3) & 1) * 8;
    const int vrow = (l & 7) + (((l >> 3) & 1) << 3);
    const int vcol = (l >> 4) * 8;

    for (int kt = 0; kt < NT; kt++) {
        if (kt < NT - 2) cp_wait<2>();
        else if (kt == NT - 2) cp_wait<1>();
        else cp_wait<0>();
        __syncthreads();
        if (kt + 3 < NT) loadKV(kt + 3);

        const __half* Kt = sK + (size_t)(kt & (NSTG - 1)) * TKA * SQL;
        const __half* Vt = sV + (size_t)(kt & (NSTG - 1)) * TKA * SQL;

        float s[8][4];
#pragma unroll
        for (int j = 0; j < 8; j++)
#pragma unroll
            for (int i = 0; i < 4; i++) s[j][i] = 0.0f;
#pragma unroll
        for (int dc = 0; dc < 8; dc++) {
#pragma unroll
            for (int np = 0; np < 4; np++) {
                uint32_t b0, b1, b2, b3;
                ldsm_x4(smaddr(Kt + (np * 16 + krow) * SQL + dc * 16 + kcol),
                        b0, b1, b2, b3);
                mma16816(s[2 * np],     qa[dc], b0, b1);
                mma16816(s[2 * np + 1], qa[dc], b2, b3);
            }
        }

        // online softmax in exp2 domain (scores already scaled by log2e/sqrt(d))
        float mx0 = -1e30f, mx1 = -1e30f;
#pragma unroll
        for (int j = 0; j < 8; j++) {
            mx0 = fmaxf(mx0, fmaxf(s[j][0], s[j][1]));
            mx1 = fmaxf(mx1, fmaxf(s[j][2], s[j][3]));
        }
        mx0 = fmaxf(mx0, __shfl_xor_sync(0xffffffffu, mx0, 1));
        mx0 = fmaxf(mx0, __shfl_xor_sync(0xffffffffu, mx0, 2));
        mx1 = fmaxf(mx1, __shfl_xor_sync(0xffffffffu, mx1, 1));
        mx1 = fmaxf(mx1, __shfl_xor_sync(0xffffffffu, mx1, 2));
        float mn0 = fmaxf(m0, mx0), mn1 = fmaxf(m1, mx1);

        float f0 = 1.0f, f1 = 1.0f;
        bool upd = (mn0 > m0) || (mn1 > m1);
        if (__any_sync(0xffffffffu, upd)) {
            f0 = exp2f(m0 - mn0); f1 = exp2f(m1 - mn1);
            m0 = mn0; m1 = mn1;
#pragma unroll
            for (int j = 0; j < 16; j++) {
                o[j][0] *= f0; o[j][1] *= f0;
                o[j][2] *= f1; o[j][3] *= f1;
            }
        }

        float sum0 = 0.0f, sum1 = 0.0f;
#pragma unroll
        for (int j = 0; j < 8; j++) {
            s[j][0] = exp2f(s[j][0] - mn0);
            s[j][1] = exp2f(s[j][1] - mn0);
            s[j][2] = exp2f(s[j][2] - mn1);
            s[j][3] = exp2f(s[j][3] - mn1);
            sum0 += s[j][0] + s[j][1];
            sum1 += s[j][2] + s[j][3];
        }
        sum0 += __shfl_xor_sync(0xffffffffu, sum0, 1);
        sum0 += __shfl_xor_sync(0xffffffffu, sum0, 2);
        sum1 += __shfl_xor_sync(0xffffffffu, sum1, 1);
        sum1 += __shfl_xor_sync(0xffffffffu, sum1, 2);
        l0 = l0 * f0 + sum0;
        l1 = l1 * f1 + sum1;

#pragma unroll
        for (int t = 0; t < 4; t++) {
            uint32_t pa[4];
            pa[0] = h2pack(s[2 * t][0],     s[2 * t][1]);
            pa[1] = h2pack(s[2 * t][2],     s[2 * t][3]);
            pa[2] = h2pack(s[2 * t + 1][0], s[2 * t + 1][1]);
            pa[3] = h2pack(s[2 * t + 1][2], s[2 * t + 1][3]);
#pragma unroll
            for (int npp = 0; npp < 8; npp++) {
                uint32_t b0, b1, b2, b3;
                ldsm_x4_t(smaddr(Vt + (t * 16 + vrow) * SQL + npp * 16 + vcol),
                          b0, b1, b2, b3);
                mma16816(o[2 * npp],     pa, b0, b1);
                mma16816(o[2 * npp + 1], pa, b2, b3);
            }
        }
    }

    float inv0 = 1.0f / l0, inv1 = 1.0f / l1;
    int grow = b * SEQ + q0 + w * 16 + (l >> 2);
    __half* O0 = g_attn + (size_t)grow * (NH * HD) + h * HD;
    __half* O1 = O0 + (size_t)8 * (NH * HD);
#pragma unroll
    for (int j = 0; j < 16; j++) {
        int col = j * 8 + 2 * (l & 3);
        *(__half2*)(O0 + col) = __floats2half2_rn(o[j][0] * inv0, o[j][1] * inv0);
        *(__half2*)(O1 + col) = __floats2half2_rn(o[j][2] * inv1, o[j][3] * inv1);
    }
}

// ---------------- launch ----------------
extern "C" void kernel_launch(void* const* d_in, const int* in_sizes, int n_in,
                              void* d_out, int out_size)
{
    const float* hidden = (const float*)d_in[0];
    const float* Wq = (const float*)d_in[1];
    const float* Wk = (const float*)d_in[2];
    const float* Wv = (const float*)d_in[3];
    const float* Wo = (const float*)d_in[4];
    float* out = (float*)d_out;

    cudaFuncSetAttribute(attn_kernel, cudaFuncAttributeMaxDynamicSharedMemorySize, ATTN_SMEM);
    cudaFuncSetAttribute(gemm_tn, cudaFuncAttributeMaxDynamicSharedMemorySize, GEMM_SMEM);

    __half *p_hX, *p_Wq, *p_Wkv, *p_Wo, *p_Q, *p_K, *p_V, *p_attn;
    cudaGetSymbolAddress((void**)&p_hX,  g_hX);
    cudaGetSymbolAddress((void**)&p_Wq,  g_Wq);
    cudaGetSymbolAddress((void**)&p_Wkv, g_Wkv);
    cudaGetSymbolAddress((void**)&p_Wo,  g_Wo);
    cudaGetSymbolAddress((void**)&p_attn, g_attn);
    cudaGetSymbolAddress((void**)&p_Q, g_Q);
    cudaGetSymbolAddress((void**)&p_K, g_K);
    cudaGetSymbolAddress((void**)&p_V, g_V);

    const int T = 256;
    f2h4_kernel<<<(MROWS*HID/4 + T-1)/T, T>>>((const float4*)hidden, p_hX, MROWS*HID/4);
    f2h4_kernel<<<(NH*HD*HID/4 + T-1)/T, T>>>((const float4*)Wq, p_Wq, NH*HD*HID/4);
    f2h4_kernel<<<(NKV*HD*HID/4 + T-1)/T, T>>>((const float4*)Wk, p_Wkv, NKV*HD*HID/4);
    f2h4_kernel<<<(NKV*HD*HID/4 + T-1)/T, T>>>((const float4*)Wv, p_Wkv + (size_t)NKV*HD*HID, NKV*HD*HID/4);
    f2h4_kernel<<<(HID*NH*HD/4 + T-1)/T, T>>>((const float4*)Wo, p_Wo, HID*NH*HD/4);

    tab_kernel<<<(SEQ*64 + T-1)/T, T>>>();

    // fused projections: Q (rope -> g_Q), KV (rope K -> g_K, V -> g_V)
    gemm_tn<<<dim3((NH*HD)/GBN,    MROWS/GBM), T, GEMM_SMEM>>>(
        p_hX, p_Wq,  (float*)nullptr, p_Q, ((__half*)nullptr), MROWS, NH*HD,    HID, 1);
    gemm_tn<<<dim3((2*NKV*HD)/GBN, MROWS/GBM), T, GEMM_SMEM>>>(
        p_hX, p_Wkv, (float*)nullptr, p_K, p_V,                MROWS, 2*NKV*HD, HID, 2);

    attn_kernel<<<dim3(SEQ/TQA, BB*NH), T, ATTN_SMEM>>>();

    // output projection -> fp32 d_out
    gemm_tn<<<dim3(HID/GBN, MROWS/GBM), T, GEMM_SMEM>>>(
        p_attn, p_Wo, out, (__half*)nullptr, (__half*)nullptr, MROWS, HID, NH*HD, 0);
}

// round 9
// speedup vs baseline: 2.0891x; 1.0293x over previous
#include <cuda_runtime.h>
#include <cuda_fp16.h>
#include <math.h>
#include <stdint.h>
#include <cstdint>

#define NH   16
#define NKV  4
#define HD   128
#define BB   2
#define SEQ  2048
#define HID  2048
#define MROWS (BB*SEQ)

// scale folded into Q: (1/sqrt(128)) * log2(e)
#define QSCL 0.1275174337f

// ---------------- device scratch ----------------
__device__ __half g_hX [MROWS*HID];
__device__ __half g_Wq [NH*HD*HID];
__device__ __half g_Wkv[(2*NKV*HD)*HID];
__device__ __half g_Wo [HID*NH*HD];
__device__ __half g_Q  [BB*NH*SEQ*HD];     // roped, pre-scaled by QSCL
__device__ __half g_K  [BB*NKV*SEQ*HD];    // roped
__device__ __half g_V  [BB*NKV*SEQ*HD];
__device__ __half g_attn[MROWS*NH*HD];
__device__ float  g_cos[SEQ*64];
__device__ float  g_sin[SEQ*64];

// ---------------- cp.async helpers ----------------
__device__ __forceinline__ void cp_async16(void* smem, const void* gmem)
{
    unsigned s = (unsigned)__cvta_generic_to_shared(smem);
    asm volatile("cp.async.cg.shared.global [%0], [%1], 16;\n" :: "r"(s), "l"(gmem));
}
__device__ __forceinline__ void cp_commit() { asm volatile("cp.async.commit_group;\n"); }
template<int N> __device__ __forceinline__ void cp_wait()
{
    asm volatile("cp.async.wait_group %0;\n" :: "n"(N));
}

// ---------------- mma / ldmatrix primitives ----------------
__device__ __forceinline__ uint32_t smaddr(const void* p)
{
    return (uint32_t)__cvta_generic_to_shared(p);
}
__device__ __forceinline__ void ldsm_x4(uint32_t a, uint32_t& r0, uint32_t& r1,
                                        uint32_t& r2, uint32_t& r3)
{
    asm volatile("ldmatrix.sync.aligned.m8n8.x4.shared.b16 {%0,%1,%2,%3}, [%4];"
                 : "=r"(r0), "=r"(r1), "=r"(r2), "=r"(r3) : "r"(a));
}
__device__ __forceinline__ void ldsm_x4_t(uint32_t a, uint32_t& r0, uint32_t& r1,
                                          uint32_t& r2, uint32_t& r3)
{
    asm volatile("ldmatrix.sync.aligned.m8n8.x4.trans.shared.b16 {%0,%1,%2,%3}, [%4];"
                 : "=r"(r0), "=r"(r1), "=r"(r2), "=r"(r3) : "r"(a));
}
__device__ __forceinline__ void mma16816(float* c, const uint32_t* a, uint32_t b0, uint32_t b1)
{
    asm volatile("mma.sync.aligned.m16n8k16.row.col.f32.f16.f16.f32 "
                 "{%0,%1,%2,%3}, {%4,%5,%6,%7}, {%8,%9}, {%0,%1,%2,%3};"
                 : "+f"(c[0]), "+f"(c[1]), "+f"(c[2]), "+f"(c[3])
                 : "r"(a[0]), "r"(a[1]), "r"(a[2]), "r"(a[3]), "r"(b0), "r"(b1));
}
__device__ __forceinline__ uint32_t h2pack(float x, float y)
{
    __half2 h = __floats2half2_rn(x, y);
    return *(uint32_t*)&h;
}

// ---------------- merged fp32 -> fp16 conversion (one launch for all 5 tensors) ----------
// float4 segment sizes: hX 2097152 | Wq 1048576 | Wk 524288 | Wv 524288 | Wo 1048576
#define SEG0 2097152L
#define SEG1 (SEG0 + 1048576L)
#define SEG2 (SEG1 + 524288L)
#define SEG3 (SEG2 + 524288L)
#define SEG4 (SEG3 + 1048576L)      // 5242880 total
#define F2H_BLOCKS (SEG4 / 256)

__global__ void f2h_all(const float4* __restrict__ hX, const float4* __restrict__ Wq,
                        const float4* __restrict__ Wk, const float4* __restrict__ Wv,
                        const float4* __restrict__ Wo)
{
    long i = (long)blockIdx.x * 256 + threadIdx.x;
    const float4* src; __half* dst; long off;
    if (i < SEG0)      { src = hX; dst = g_hX;  off = i; }
    else if (i < SEG1) { src = Wq; dst = g_Wq;  off = i - SEG0; }
    else if (i < SEG2) { src = Wk; dst = g_Wkv; off = i - SEG1; }
    else if (i < SEG3) { src = Wv; dst = g_Wkv + (size_t)NKV*HD*HID; off = i - SEG2; }
    else               { src = Wo; dst = g_Wo;  off = i - SEG3; }
    float4 v = src[off];
    __half2* d = (__half2*)(dst + off * 4);
    d[0] = __floats2half2_rn(v.x, v.y);
    d[1] = __floats2half2_rn(v.z, v.w);
}

// ---------------- RoPE table ----------------
__global__ void tab_kernel()
{
    int tid = blockIdx.x * blockDim.x + threadIdx.x;
    if (tid >= SEQ * 64) return;
    int s = tid / 64, i = tid % 64;
    double inv = pow(10000.0, -(double)i / 64.0);
    double ang = (double)s * inv;
    double sn, cs;
    sincos(ang, &sn, &cs);
    g_cos[tid] = (float)cs;
    g_sin[tid] = (float)sn;
}

// ======== Raw-mma TN GEMM with fused epilogues (unchanged from R8) ========
#define GBM 128
#define GBN 128
#define GBK 64
#define GST 72
#define GNSTG 3
#define GEMM_SMEM (GNSTG*(GBM+GBN)*GST*2)    // 110592 B
#define EST 132

__global__ void __launch_bounds__(256, 2) gemm_tn(const __half* __restrict__ A,
                                                  const __half* __restrict__ Bm,
                                                  float* __restrict__ C,
                                                  __half* __restrict__ hK,
                                                  __half* __restrict__ hV,
                                                  int M, int N, int K, int mode)
{
    extern __shared__ __align__(16) __half sm[];
    const int tid = threadIdx.x;
    const int w = tid >> 5, l = tid & 31;
    const int wm = w >> 2, wn = w & 3;
    const int m0 = blockIdx.y * GBM, n0 = blockIdx.x * GBN;
    const int NT = K / GBK;
    const int stageH = (GBM + GBN) * GST;

    auto loadStage = [&](int t) {
        __half* sA = sm + (size_t)(t % GNSTG) * stageH;
        __half* sB = sA + GBM * GST;
        const __half* Ag = A + (size_t)m0 * K + t * GBK;
        const __half* Bg = Bm + (size_t)n0 * K + t * GBK;
#pragma unroll
        for (int i = 0; i < 4; i++) {
            int u = tid + i * 256;
            int r = u >> 3, c = (u & 7) * 8;
            cp_async16(sA + r * GST + c, Ag + (size_t)r * K + c);
        }
#pragma unroll
        for (int i = 0; i < 4; i++) {
            int u = tid + i * 256;
            int r = u >> 3, c = (u & 7) * 8;
            cp_async16(sB + r * GST + c, Bg + (size_t)r * K + c);
        }
        cp_commit();
    };

    loadStage(0); loadStage(1);

    float acc[4][4][4];
#pragma unroll
    for (int mi = 0; mi < 4; mi++)
#pragma unroll
        for (int nj = 0; nj < 4; nj++)
#pragma unroll
            for (int e = 0; e < 4; e++) acc[mi][nj][e] = 0.0f;

    const int arow_l = (l & 15);
    const int acoff  = (l >> 4) * 8;
    const int krow   = (l & 7) + ((l >> 4) << 3);
    const int kcol   = ((l >> 3) & 1) * 8;

    for (int t = 0; t < NT; t++) {
        if (t < NT - 1) cp_wait<1>(); else cp_wait<0>();
        __syncthreads();
        if (t + 2 < NT) loadStage(t + 2);

        const __half* sA = sm + (size_t)(t % GNSTG) * stageH;
        const __half* sB = sA + GBM * GST;

#pragma unroll
        for (int dc = 0; dc < 4; dc++) {
            uint32_t a[4][4];
#pragma unroll
            for (int mi = 0; mi < 4; mi++)
                ldsm_x4(smaddr(sA + (wm * 64 + mi * 16 + arow_l) * GST + dc * 16 + acoff),
                        a[mi][0], a[mi][1], a[mi][2], a[mi][3]);
#pragma unroll
            for (int np = 0; np < 2; np++) {
                uint32_t b0, b1, b2, b3;
                ldsm_x4(smaddr(sB + (wn * 32 + np * 16 + krow) * GST + dc * 16 + kcol),
                        b0, b1, b2, b3);
#pragma unroll
                for (int mi = 0; mi < 4; mi++) {
                    mma16816(acc[mi][2 * np],     a[mi], b0, b1);
                    mma16816(acc[mi][2 * np + 1], a[mi], b2, b3);
                }
            }
        }
    }

    if (mode == 0) {
#pragma unroll
        for (int mi = 0; mi < 4; mi++) {
            int row = m0 + wm * 64 + mi * 16 + (l >> 2);
            float* C0 = C + (size_t)row * N + n0 + wn * 32;
            float* C1 = C0 + (size_t)8 * N;
#pragma unroll
            for (int nj = 0; nj < 4; nj++) {
                int col = nj * 8 + (l & 3) * 2;
                *(float2*)(C0 + col) = make_float2(acc[mi][nj][0], acc[mi][nj][1]);
                *(float2*)(C1 + col) = make_float2(acc[mi][nj][2], acc[mi][nj][3]);
            }
        }
        return;
    }

    __syncthreads();
    float* sC = (float*)sm;
#pragma unroll
    for (int mi = 0; mi < 4; mi++) {
        int r0 = wm * 64 + mi * 16 + (l >> 2);
#pragma unroll
        for (int nj = 0; nj < 4; nj++) {
            int c0 = wn * 32 + nj * 8 + (l & 3) * 2;
            sC[r0 * EST + c0]           = acc[mi][nj][0];
            sC[r0 * EST + c0 + 1]       = acc[mi][nj][1];
            sC[(r0 + 8) * EST + c0]     = acc[mi][nj][2];
            sC[(r0 + 8) * EST + c0 + 1] = acc[mi][nj][3];
        }
    }
    __syncthreads();

    const int bq = m0 / SEQ;
    const int sbase = m0 % SEQ;

    bool do_rope;
    float scl;
    __half* dst;
    if (mode == 1) {
        do_rope = true; scl = QSCL;
        dst = hK + ((size_t)(bq * NH + blockIdx.x) * SEQ) * HD;
    } else if (blockIdx.x < NKV) {
        do_rope = true; scl = 1.0f;
        dst = hK + ((size_t)(bq * NKV + blockIdx.x) * SEQ) * HD;
    } else {
        do_rope = false; scl = 1.0f;
        dst = hV + ((size_t)(bq * NKV + (blockIdx.x - NKV)) * SEQ) * HD;
    }

    if (do_rope) {
#pragma unroll
        for (int i = 0; i < 32; i++) {
            int u = tid + i * 256;
            int r = u >> 6, c = u & 63;
            float x1 = sC[r * EST + c], x2 = sC[r * EST + c + 64];
            int s = sbase + r;
            float cs = g_cos[s * 64 + c], sn = g_sin[s * 64 + c];
            dst[(size_t)s * HD + c]      = __float2half((x1 * cs - x2 * sn) * scl);
            dst[(size_t)s * HD + c + 64] = __float2half((x2 * cs + x1 * sn) * scl);
        }
    } else {
#pragma unroll
        for (int i = 0; i < 64; i++) {
            int u = tid + i * 256;
            int r = u >> 7, c = u & 127;
            dst[(size_t)(sbase + r) * HD + c] = __float2half(sC[r * EST + c]);
        }
    }
}

// ---------------- FA2-style flash attention (unchanged from R8) ----------------
#define TQA 128
#define TKA 64
#define SQL 136
#define NSTG 4
#define ATTN_SMEM ((TQA*SQL + 2*NSTG*TKA*SQL)*2)

__global__ void __launch_bounds__(256) attn_kernel()
{
    extern __shared__ __align__(16) char smem_raw[];
    __half* sQ = (__half*)smem_raw;
    __half* sK = sQ + TQA * SQL;
    __half* sV = sK + NSTG * TKA * SQL;

    const int tid = threadIdx.x;
    const int w = tid >> 5, l = tid & 31;
    const int q0 = blockIdx.x * TQA;
    const int bh = blockIdx.y;
    const int b = bh / NH, h = bh % NH;
    const int kvh = h / (NH / NKV);

    const __half* Qg = g_Q + ((size_t)bh * SEQ + q0) * HD;
    const __half* Kg = g_K + ((size_t)(b * NKV + kvh) * SEQ) * HD;
    const __half* Vg = g_V + ((size_t)(b * NKV + kvh) * SEQ) * HD;
    const int NT = SEQ / TKA;

#pragma unroll
    for (int i = 0; i < 8; i++) {
        int u = tid + i * 256;
        int r = u >> 4, c = (u & 15) * 8;
        cp_async16(sQ + r * SQL + c, Qg + r * HD + c);
    }
    cp_commit();

    auto loadKV = [&](int t) {
        const __half* ks = Kg + (size_t)t * TKA * HD;
        const __half* vs = Vg + (size_t)t * TKA * HD;
        __half* kd = sK + (size_t)(t & (NSTG - 1)) * TKA * SQL;
        __half* vd = sV + (size_t)(t & (NSTG - 1)) * TKA * SQL;
#pragma unroll
        for (int i = 0; i < 4; i++) {
            int u = tid + i * 256;
            int r = u >> 4, c = (u & 15) * 8;
            cp_async16(kd + r * SQL + c, ks + r * HD + c);
            cp_async16(vd + r * SQL + c, vs + r * HD + c);
        }
        cp_commit();
    };
    loadKV(0); loadKV(1); loadKV(2);

    cp_wait<3>();
    __syncthreads();

    uint32_t qa[8][4];
    {
        int qrow = w * 16 + (l & 15);
        int coff = (l >> 4) * 8;
#pragma unroll
        for (int dc = 0; dc < 8; dc++)
            ldsm_x4(smaddr(sQ + qrow * SQL + dc * 16 + coff),
                    qa[dc][0], qa[dc][1], qa[dc][2], qa[dc][3]);
    }

    float o[16][4];
#pragma unroll
    for (int j = 0; j < 16; j++)
#pragma unroll
        for (int i = 0; i < 4; i++) o[j][i] = 0.0f;
    float m0 = -1e30f, m1 = -1e30f, l0 = 0.0f, l1 = 0.0f;

    const int krow = (l & 7) + ((l >> 4) << 3);
    const int kcol = ((l >> 3) & 1) * 8;
    const int vrow = (l & 7) + (((l >> 3) & 1) << 3);
    const int vcol = (l >> 4) * 8;

    for (int kt = 0; kt < NT; kt++) {
        if (kt < NT - 2) cp_wait<2>();
        else if (kt == NT - 2) cp_wait<1>();
        else cp_wait<0>();
        __syncthreads();
        if (kt + 3 < NT) loadKV(kt + 3);

        const __half* Kt = sK + (size_t)(kt & (NSTG - 1)) * TKA * SQL;
        const __half* Vt = sV + (size_t)(kt & (NSTG - 1)) * TKA * SQL;

        float s[8][4];
#pragma unroll
        for (int j = 0; j < 8; j++)
#pragma unroll
            for (int i = 0; i < 4; i++) s[j][i] = 0.0f;
#pragma unroll
        for (int dc = 0; dc < 8; dc++) {
#pragma unroll
            for (int np = 0; np < 4; np++) {
                uint32_t b0, b1, b2, b3;
                ldsm_x4(smaddr(Kt + (np * 16 + krow) * SQL + dc * 16 + kcol),
                        b0, b1, b2, b3);
                mma16816(s[2 * np],     qa[dc], b0, b1);
                mma16816(s[2 * np + 1], qa[dc], b2, b3);
            }
        }

        float mx0 = -1e30f, mx1 = -1e30f;
#pragma unroll
        for (int j = 0; j < 8; j++) {
            mx0 = fmaxf(mx0, fmaxf(s[j][0], s[j][1]));
            mx1 = fmaxf(mx1, fmaxf(s[j][2], s[j][3]));
        }
        mx0 = fmaxf(mx0, __shfl_xor_sync(0xffffffffu, mx0, 1));
        mx0 = fmaxf(mx0, __shfl_xor_sync(0xffffffffu, mx0, 2));
        mx1 = fmaxf(mx1, __shfl_xor_sync(0xffffffffu, mx1, 1));
        mx1 = fmaxf(mx1, __shfl_xor_sync(0xffffffffu, mx1, 2));
        float mn0 = fmaxf(m0, mx0), mn1 = fmaxf(m1, mx1);

        float f0 = 1.0f, f1 = 1.0f;
        bool upd = (mn0 > m0) || (mn1 > m1);
        if (__any_sync(0xffffffffu, upd)) {
            f0 = exp2f(m0 - mn0); f1 = exp2f(m1 - mn1);
            m0 = mn0; m1 = mn1;
#pragma unroll
            for (int j = 0; j < 16; j++) {
                o[j][0] *= f0; o[j][1] *= f0;
                o[j][2] *= f1; o[j][3] *= f1;
            }
        }

        float sum0 = 0.0f, sum1 = 0.0f;
#pragma unroll
        for (int j = 0; j < 8; j++) {
            s[j][0] = exp2f(s[j][0] - mn0);
            s[j][1] = exp2f(s[j][1] - mn0);
            s[j][2] = exp2f(s[j][2] - mn1);
            s[j][3] = exp2f(s[j][3] - mn1);
            sum0 += s[j][0] + s[j][1];
            sum1 += s[j][2] + s[j][3];
        }
        sum0 += __shfl_xor_sync(0xffffffffu, sum0, 1);
        sum0 += __shfl_xor_sync(0xffffffffu, sum0, 2);
        sum1 += __shfl_xor_sync(0xffffffffu, sum1, 1);
        sum1 += __shfl_xor_sync(0xffffffffu, sum1, 2);
        l0 = l0 * f0 + sum0;
        l1 = l1 * f1 + sum1;

#pragma unroll
        for (int t = 0; t < 4; t++) {
            uint32_t pa[4];
            pa[0] = h2pack(s[2 * t][0],     s[2 * t][1]);
            pa[1] = h2pack(s[2 * t][2],     s[2 * t][3]);
            pa[2] = h2pack(s[2 * t + 1][0], s[2 * t + 1][1]);
            pa[3] = h2pack(s[2 * t + 1][2], s[2 * t + 1][3]);
#pragma unroll
            for (int npp = 0; npp < 8; npp++) {
                uint32_t b0, b1, b2, b3;
                ldsm_x4_t(smaddr(Vt + (t * 16 + vrow) * SQL + npp * 16 + vcol),
                          b0, b1, b2, b3);
                mma16816(o[2 * npp],     pa, b0, b1);
                mma16816(o[2 * npp + 1], pa, b2, b3);
            }
        }
    }

    float inv0 = 1.0f / l0, inv1 = 1.0f / l1;
    int grow = b * SEQ + q0 + w * 16 + (l >> 2);
    __half* O0 = g_attn + (size_t)grow * (NH * HD) + h * HD;
    __half* O1 = O0 + (size_t)8 * (NH * HD);
#pragma unroll
    for (int j = 0; j < 16; j++) {
        int col = j * 8 + 2 * (l & 3);
        *(__half2*)(O0 + col) = __floats2half2_rn(o[j][0] * inv0, o[j][1] * inv0);
        *(__half2*)(O1 + col) = __floats2half2_rn(o[j][2] * inv1, o[j][3] * inv1);
    }
}

// ---------------- launch ----------------
extern "C" void kernel_launch(void* const* d_in, const int* in_sizes, int n_in,
                              void* d_out, int out_size)
{
    const float* hidden = (const float*)d_in[0];
    const float* Wq = (const float*)d_in[1];
    const float* Wk = (const float*)d_in[2];
    const float* Wv = (const float*)d_in[3];
    const float* Wo = (const float*)d_in[4];
    float* out = (float*)d_out;

    // capture-safe auxiliary stream + events (created once, never destroyed)
    static cudaStream_t s_aux = nullptr;
    static cudaEvent_t  s_evA = nullptr, s_evB = nullptr;
    if (s_aux == nullptr) {
        cudaStreamCreateWithFlags(&s_aux, cudaStreamNonBlocking);
        cudaEventCreateWithFlags(&s_evA, cudaEventDisableTiming);
        cudaEventCreateWithFlags(&s_evB, cudaEventDisableTiming);
    }

    cudaFuncSetAttribute(attn_kernel, cudaFuncAttributeMaxDynamicSharedMemorySize, ATTN_SMEM);
    cudaFuncSetAttribute(gemm_tn, cudaFuncAttributeMaxDynamicSharedMemorySize, GEMM_SMEM);

    __half *p_hX, *p_Wq, *p_Wkv, *p_Wo, *p_Q, *p_K, *p_V, *p_attn;
    cudaGetSymbolAddress((void**)&p_hX,  g_hX);
    cudaGetSymbolAddress((void**)&p_Wq,  g_Wq);
    cudaGetSymbolAddress((void**)&p_Wkv, g_Wkv);
    cudaGetSymbolAddress((void**)&p_Wo,  g_Wo);
    cudaGetSymbolAddress((void**)&p_attn, g_attn);
    cudaGetSymbolAddress((void**)&p_Q, g_Q);
    cudaGetSymbolAddress((void**)&p_K, g_K);
    cudaGetSymbolAddress((void**)&p_V, g_V);

    const int T = 256;

    // (0) all conversions in one launch
    f2h_all<<<F2H_BLOCKS, T>>>((const float4*)hidden, (const float4*)Wq,
                               (const float4*)Wk, (const float4*)Wv, (const float4*)Wo);
    // (1) rope table
    tab_kernel<<<(SEQ*64 + T-1)/T, T>>>();

    // fork: gemmQ on aux stream, gemmKV on main stream (independent)
    cudaEventRecord(s_evA, 0);
    cudaStreamWaitEvent(s_aux, s_evA, 0);
    // (2) Q projection + rope -> g_Q   [aux stream]
    gemm_tn<<<dim3((NH*HD)/GBN, MROWS/GBM), T, GEMM_SMEM, s_aux>>>(
        p_hX, p_Wq, (float*)nullptr, p_Q, (__half*)nullptr, MROWS, NH*HD, HID, 1);
    // (3) KV projection + rope K -> g_K, V -> g_V   [main stream]
    gemm_tn<<<dim3((2*NKV*HD)/GBN, MROWS/GBM), T, GEMM_SMEM>>>(
        p_hX, p_Wkv, (float*)nullptr, p_K, p_V, MROWS, 2*NKV*HD, HID, 2);
    // join
    cudaEventRecord(s_evB, s_aux);
    cudaStreamWaitEvent(0, s_evB, 0);

    // (4) attention
    attn_kernel<<<dim3(SEQ/TQA, BB*NH), T, ATTN_SMEM>>>();

    // (5) output projection -> fp32 d_out   (profile index 5 -> ncu shows this)
    gemm_tn<<<dim3(HID/GBN, MROWS/GBM), T, GEMM_SMEM>>>(
        p_attn, p_Wo, out, (__half*)nullptr, (__half*)nullptr, MROWS, HID, NH*HD, 0);
}